// round 8
// baseline (speedup 1.0000x reference)
#include <cuda_runtime.h>
#include <math.h>

#define N_NODES 50000
#define N_EDGES 800000
#define IN_DIM  128
#define HID     96
#define OUT_DIM 64
#define MAX_REC 5
#define SCAN_NB ((N_NODES + 1023) / 1024)   // 49

typedef unsigned long long u64;

// ---------------- scratch (no allocations allowed) ----------------
__device__ float g_h[N_NODES * HID];
__device__ float g_agg[N_NODES * HID];
__device__ int   g_steps[N_NODES];
__device__ int   g_deg[N_NODES];
__device__ int   g_rowoff[N_NODES + 1];
__device__ int   g_cursor[N_NODES];
__device__ int   g_col[N_EDGES];
__device__ int   g_hist[8];
__device__ int   g_bcur[8];
__device__ int   g_order[N_NODES];
__device__ int   g_cnt[8];
__device__ int   g_bsum[64];
__device__ int   g_boff[64];
__device__ float g_wt_ih[3 * HID * HID];   // [chunk][k][j]
__device__ float g_wt_hh[3 * HID * HID];

// ---------------- f32x2 helpers ----------------
__device__ __forceinline__ u64 ffma2(u64 a, u64 b, u64 c) {
    u64 d;
    asm("fma.rn.f32x2 %0, %1, %2, %3;" : "=l"(d) : "l"(a), "l"(b), "l"(c));
    return d;
}
__device__ __forceinline__ u64 pack2(float x, float y) {
    u64 r;
    asm("mov.b64 %0, {%1, %2};" : "=l"(r) : "f"(x), "f"(y));
    return r;
}
__device__ __forceinline__ float2 unpack2(u64 v) {
    float2 r;
    asm("mov.b64 {%0, %1}, %2;" : "=f"(r.x), "=f"(r.y) : "l"(v));
    return r;
}
__device__ __forceinline__ float fast_sigmoid(float x) {
    return __fdividef(1.f, 1.f + __expf(-x));
}
__device__ __forceinline__ float fast_tanh(float x) {
    return 1.f - __fdividef(2.f, __expf(2.f * x) + 1.f);
}

// ---------------- fused init + weight transpose ----------------
__global__ void k_initwt(const float* __restrict__ wih, const float* __restrict__ whh) {
    int i = blockIdx.x * 256 + threadIdx.x;
    if (i < N_NODES) g_deg[i] = 0;
    if (i < 8) g_hist[i] = 0;
    if (i < 3 * HID * HID) {
        int chunk = i / (HID * HID);
        int r = i - chunk * HID * HID;
        int k = r / HID, j = r - k * HID;
        g_wt_ih[i] = wih[(chunk * HID + j) * HID + k];
        g_wt_hh[i] = whh[(chunk * HID + j) * HID + k];
    }
}

// ---------------- degree histogram ----------------
__global__ void k_deg(const int* __restrict__ ei) {
    int e = blockIdx.x * blockDim.x + threadIdx.x;
    if (e < N_EDGES) atomicAdd(&g_deg[ei[e]], 1);
}

// ---------------- multi-block scan ----------------
__global__ __launch_bounds__(1024) void k_scan1() {
    __shared__ int wsum[32];
    __shared__ int woff[32];
    int t = threadIdx.x, lane = t & 31, wid = t >> 5;
    int i = blockIdx.x * 1024 + t;
    int v = (i < N_NODES) ? g_deg[i] : 0;
    int s = v;
#pragma unroll
    for (int o = 1; o < 32; o <<= 1) {
        int u = __shfl_up_sync(0xffffffffu, s, o);
        if (lane >= o) s += u;
    }
    if (lane == 31) wsum[wid] = s;
    __syncthreads();
    if (wid == 0) {
        int ws = wsum[lane];
        int ss = ws;
#pragma unroll
        for (int o = 1; o < 32; o <<= 1) {
            int u = __shfl_up_sync(0xffffffffu, ss, o);
            if (lane >= o) ss += u;
        }
        woff[lane] = ss - ws;
        if (lane == 31) g_bsum[blockIdx.x] = ss;
    }
    __syncthreads();
    if (i < N_NODES) g_rowoff[i] = s - v + woff[wid];
}

// ---------------- fused input GEMM + relu + tau/steps ----------------
__global__ __launch_bounds__(256) void k_input(
    const float* __restrict__ x, const float* __restrict__ w_in,
    const float* __restrict__ b_in, const float* __restrict__ tw1,
    const float* __restrict__ tb1, const float* __restrict__ tw2,
    const float* __restrict__ tb2)
{
    extern __shared__ float sm_in[];
    float* xs_t = sm_in;               // [128][66]
    float* ts   = xs_t + 128 * 66;     // [128][16]
    int t = threadIdx.x;
    int node0 = blockIdx.x * 64;

#pragma unroll
    for (int idx = t; idx < 128 * 16; idx += 256) ts[idx] = tw1[idx];
#pragma unroll
    for (int idx = t; idx < 64 * 128; idx += 256) {
        int n = idx >> 7, k = idx & 127;
        int gn = node0 + n;
        xs_t[k * 66 + n] = (gn < N_NODES) ? x[gn * IN_DIM + k] : 0.f;
    }
    __syncthreads();

    int cj = t & 31;     // cols {cj, cj+32, cj+64}
    int pg = t >> 5;     // node pairs {pg, pg+8, pg+16, pg+24}

    u64 acc[3][4];
#pragma unroll
    for (int cc = 0; cc < 3; cc++) {
        float b = b_in[cj + 32 * cc];
        u64 bp = pack2(b, b);
#pragma unroll
        for (int q = 0; q < 4; q++) acc[cc][q] = bp;
    }
#pragma unroll 8
    for (int k = 0; k < 128; k++) {
        u64 wd[3];
#pragma unroll
        for (int cc = 0; cc < 3; cc++) {
            float w = __ldg(&w_in[k * 96 + cj + 32 * cc]);
            wd[cc] = pack2(w, w);
        }
        u64 ap[4];
#pragma unroll
        for (int q = 0; q < 4; q++)
            ap[q] = *(const u64*)&xs_t[k * 66 + 2 * (pg + 8 * q)];
#pragma unroll
        for (int cc = 0; cc < 3; cc++)
#pragma unroll
            for (int q = 0; q < 4; q++)
                acc[cc][q] = ffma2(wd[cc], ap[q], acc[cc][q]);
    }
#pragma unroll
    for (int cc = 0; cc < 3; cc++) {
        int col = cj + 32 * cc;
#pragma unroll
        for (int q = 0; q < 4; q++) {
            int n0 = node0 + 2 * (pg + 8 * q);
            float2 g = unpack2(acc[cc][q]);
            if (n0 < N_NODES)     g_h[n0 * HID + col]       = fmaxf(g.x, 0.f);
            if (n0 + 1 < N_NODES) g_h[(n0 + 1) * HID + col] = fmaxf(g.y, 0.f);
        }
    }

    // tau: 4 threads per node
    {
        int tn = t >> 2;
        int tj = t & 3;
        int gn = node0 + tn;
        float hh[4];
#pragma unroll
        for (int u = 0; u < 4; u++) hh[u] = tb1[tj + 4 * u];
#pragma unroll 4
        for (int k = 0; k < 128; k++) {
            float xv = xs_t[k * 66 + tn];
#pragma unroll
            for (int u = 0; u < 4; u++)
                hh[u] += xv * ts[k * 16 + tj + 4 * u];
        }
        float s = 0.f;
#pragma unroll
        for (int u = 0; u < 4; u++)
            s += fmaxf(hh[u], 0.f) * tw2[tj + 4 * u];
        s += __shfl_xor_sync(0xffffffffu, s, 1);
        s += __shfl_xor_sync(0xffffffffu, s, 2);
        if (tj == 0 && gn < N_NODES) {
            s += tb2[0];
            float sp = fmaxf(s, 0.f) + log1pf(expf(-fabsf(s)));
            float inv = 1.0f / sp;
            int st = (inv >= (float)MAX_REC) ? MAX_REC : (int)inv;
            g_steps[gn] = st;
            atomicAdd(&g_hist[st], 1);
        }
    }
}

__global__ void k_scan2() {
    __shared__ int sh[64];
    int t = threadIdx.x;
    sh[t] = (t < SCAN_NB) ? g_bsum[t] : 0;
    __syncthreads();
    if (t == 0) {
        int run = 0;
        for (int b = 0; b < SCAN_NB; b++) { g_boff[b] = run; run += sh[b]; }
        g_rowoff[N_NODES] = run;
        int suffix = 0;
        int start[6];
        for (int s = 5; s >= 0; s--) { start[s] = suffix; suffix += g_hist[s]; }
        for (int s = 0; s < 6; s++) g_bcur[s] = start[s];
        for (int it = 0; it < 5; it++) g_cnt[it] = start[it];
    }
}

// scan3 + order fused
__global__ __launch_bounds__(1024) void k_scan3() {
    int i = blockIdx.x * 1024 + threadIdx.x;
    if (i < N_NODES) {
        int v = g_rowoff[i] + g_boff[blockIdx.x];
        g_rowoff[i] = v;
        g_cursor[i] = v;
        int s = g_steps[i];
        int pos = atomicAdd(&g_bcur[s], 1);
        g_order[pos] = i;
    }
}

// ---------------- CSR fill ----------------
__global__ void k_csr(const int* __restrict__ ei) {
    int e = blockIdx.x * blockDim.x + threadIdx.x;
    if (e < N_EDGES) {
        int r = ei[e];
        int c = ei[N_EDGES + e];
        int pos = atomicAdd(&g_cursor[r], 1);
        g_col[pos] = c;
    }
}

// ---------------- edge aggregation: warp/node, 8 edges in flight ----------------
__global__ __launch_bounds__(256) void k_agg(int it) {
    int w = blockIdx.x * 8 + (threadIdx.x >> 5);
    if (w >= g_cnt[it]) return;
    int node = g_order[w];
    int lane = threadIdx.x & 31;
    int grp = lane >> 2;
    int l4  = lane & 3;
    int base = g_rowoff[node], end = g_rowoff[node + 1];

    const float4* hi4 = (const float4*)(g_h + node * HID);
    float4 hi[6], acc[6];
#pragma unroll
    for (int u = 0; u < 6; u++) {
        hi[u] = hi4[l4 + 4 * u];
        acc[u] = make_float4(0.f, 0.f, 0.f, 0.f);
    }

#pragma unroll 2
    for (int e = base + grp; e < end; e += 8) {
        int cc = __ldg(&g_col[e]);
        const float4* hp = (const float4*)(g_h + cc * HID);
#pragma unroll
        for (int u = 0; u < 6; u++) {
            float4 v = hp[l4 + 4 * u];
            acc[u].x += fabsf(v.x - hi[u].x);
            acc[u].y += fabsf(v.y - hi[u].y);
            acc[u].z += fabsf(v.z - hi[u].z);
            acc[u].w += fabsf(v.w - hi[u].w);
        }
    }
#pragma unroll
    for (int off = 4; off < 32; off <<= 1) {
#pragma unroll
        for (int u = 0; u < 6; u++) {
            acc[u].x += __shfl_xor_sync(0xffffffffu, acc[u].x, off);
            acc[u].y += __shfl_xor_sync(0xffffffffu, acc[u].y, off);
            acc[u].z += __shfl_xor_sync(0xffffffffu, acc[u].z, off);
            acc[u].w += __shfl_xor_sync(0xffffffffu, acc[u].w, off);
        }
    }
    if (grp == 0) {
        float4* ar = (float4*)(g_agg + (long long)node * HID);
#pragma unroll
        for (int u = 0; u < 6; u++) ar[l4 + 4 * u] = acc[u];
    }
}

// ---------------- GRU v5: weights via LDG.64, acts in smem, 2 blocks/SM ------
// 64 nodes/tile, 256 threads. cp = t&15 -> col-pairs {cp, cp+16, cp+32};
// ng = t>>4 -> nodes {4ng..4ng+3}.
// smem: agg_s[64][100] + h_s[64][100] + nodes[64]  = ~51.5KB -> 2 blocks/SM
__global__ __launch_bounds__(256, 2) void k_gru(
    const float* __restrict__ bih, const float* __restrict__ bhh, int it)
{
    extern __shared__ float sm_g[];
    float* agg_s = sm_g;                 // 6400
    float* h_s   = agg_s + 6400;         // 6400
    int* nodes_s = (int*)(h_s + 6400);

    int t = threadIdx.x;
    int cnt = g_cnt[it];
    int tile0 = blockIdx.x * 64;
    if (tile0 >= cnt) return;
    int nvalid = min(64, cnt - tile0);

    if (t < 64) nodes_s[t] = g_order[tile0 + min(t, nvalid - 1)];
    __syncthreads();
#pragma unroll
    for (int idx = t; idx < 64 * 24; idx += 256) {
        int n = idx / 24, c4 = idx - n * 24;
        int gn = nodes_s[n];
        ((float4*)(agg_s + n * 100))[c4] = ((const float4*)(g_agg + gn * HID))[c4];
        ((float4*)(h_s + n * 100))[c4]   = ((const float4*)(g_h + gn * HID))[c4];
    }
    __syncthreads();

    int cp = t & 15;     // col-pairs {cp, cp+16, cp+32} (cols 2p, 2p+1)
    int ng = t >> 4;     // nodes 4ng..4ng+3
    int nb = 4 * ng;

    const u64* WI = (const u64*)g_wt_ih;   // u64 index: (chunk*96 + k)*48 + p
    const u64* WH = (const u64*)g_wt_hh;

    u64 accR[3][4], accZ[3][4];
#pragma unroll
    for (int cc = 0; cc < 3; cc++) {
        int c2 = 2 * (cp + 16 * cc);
        float2 bi0 = *(const float2*)&bih[c2];
        float2 bh0 = *(const float2*)&bhh[c2];
        float2 bi1 = *(const float2*)&bih[96 + c2];
        float2 bh1 = *(const float2*)&bhh[96 + c2];
        u64 bR = pack2(bi0.x + bh0.x, bi0.y + bh0.y);
        u64 bZ = pack2(bi1.x + bh1.x, bi1.y + bh1.y);
#pragma unroll
        for (int q = 0; q < 4; q++) { accR[cc][q] = bR; accZ[cc][q] = bZ; }
    }
#pragma unroll 4
    for (int k = 0; k < 96; k++) {
        u64 wra[3], wrb[3], wza[3], wzb[3];
#pragma unroll
        for (int cc = 0; cc < 3; cc++) {
            int p = cp + 16 * cc;
            wra[cc] = __ldg(&WI[k * 48 + p]);
            wrb[cc] = __ldg(&WH[k * 48 + p]);
            wza[cc] = __ldg(&WI[(96 + k) * 48 + p]);
            wzb[cc] = __ldg(&WH[(96 + k) * 48 + p]);
        }
        u64 a2[4], h2[4];
#pragma unroll
        for (int q = 0; q < 4; q++) {
            float a  = agg_s[(nb + q) * 100 + k];
            float hv = h_s[(nb + q) * 100 + k];
            a2[q] = pack2(a, a);
            h2[q] = pack2(hv, hv);
        }
#pragma unroll
        for (int cc = 0; cc < 3; cc++)
#pragma unroll
            for (int q = 0; q < 4; q++) {
                accR[cc][q] = ffma2(wra[cc], a2[q], accR[cc][q]);
                accR[cc][q] = ffma2(wrb[cc], h2[q], accR[cc][q]);
                accZ[cc][q] = ffma2(wza[cc], a2[q], accZ[cc][q]);
                accZ[cc][q] = ffma2(wzb[cc], h2[q], accZ[cc][q]);
            }
    }
    u64 r_g[3][4], z_g[3][4];
#pragma unroll
    for (int cc = 0; cc < 3; cc++)
#pragma unroll
        for (int q = 0; q < 4; q++) {
            float2 gr = unpack2(accR[cc][q]);
            float2 gz = unpack2(accZ[cc][q]);
            r_g[cc][q] = pack2(fast_sigmoid(gr.x), fast_sigmoid(gr.y));
            z_g[cc][q] = pack2(fast_sigmoid(gz.x), fast_sigmoid(gz.y));
        }

    // candidate gate (chunk 2) — weights via LDG, no restage, no syncs
    u64 ai[3][4], ah[3][4];
#pragma unroll
    for (int cc = 0; cc < 3; cc++) {
        int c2 = 2 * (cp + 16 * cc);
        float2 b1 = *(const float2*)&bih[192 + c2];
        float2 b2 = *(const float2*)&bhh[192 + c2];
        u64 p1 = pack2(b1.x, b1.y), p2 = pack2(b2.x, b2.y);
#pragma unroll
        for (int q = 0; q < 4; q++) { ai[cc][q] = p1; ah[cc][q] = p2; }
    }
#pragma unroll 4
    for (int k = 0; k < 96; k++) {
        u64 wa[3], wb[3];
#pragma unroll
        for (int cc = 0; cc < 3; cc++) {
            int p = cp + 16 * cc;
            wa[cc] = __ldg(&WI[(192 + k) * 48 + p]);
            wb[cc] = __ldg(&WH[(192 + k) * 48 + p]);
        }
        u64 a2[4], h2[4];
#pragma unroll
        for (int q = 0; q < 4; q++) {
            float a  = agg_s[(nb + q) * 100 + k];
            float hv = h_s[(nb + q) * 100 + k];
            a2[q] = pack2(a, a);
            h2[q] = pack2(hv, hv);
        }
#pragma unroll
        for (int cc = 0; cc < 3; cc++)
#pragma unroll
            for (int q = 0; q < 4; q++) {
                ai[cc][q] = ffma2(wa[cc], a2[q], ai[cc][q]);
                ah[cc][q] = ffma2(wb[cc], h2[q], ah[cc][q]);
            }
    }
#pragma unroll
    for (int cc = 0; cc < 3; cc++) {
        int c2 = 2 * (cp + 16 * cc);
#pragma unroll
        for (int q = 0; q < 4; q++) {
            int n = nb + q;
            float2 vi = unpack2(ai[cc][q]);
            float2 vh = unpack2(ah[cc][q]);
            float2 rr = unpack2(r_g[cc][q]);
            float2 zz = unpack2(z_g[cc][q]);
            float hold0 = h_s[n * 100 + c2];
            float hold1 = h_s[n * 100 + c2 + 1];
            float nv0 = fast_tanh(vi.x + rr.x * vh.x);
            float nv1 = fast_tanh(vi.y + rr.y * vh.y);
            float h0 = (1.f - zz.x) * nv0 + zz.x * hold0;
            float h1 = (1.f - zz.y) * nv1 + zz.y * hold1;
            *(float2*)&g_h[nodes_s[n] * HID + c2] = make_float2(h0, h1);
        }
    }
}

// ---------------- output GEMM ----------------
__global__ __launch_bounds__(256) void k_out(
    const float* __restrict__ wo, const float* __restrict__ bo,
    float* __restrict__ out)
{
    __shared__ float ws[96 * 64];
    __shared__ float hs[32 * 97];
    int t = threadIdx.x;
    int node0 = blockIdx.x * 32;
#pragma unroll
    for (int idx = t; idx < 96 * 64; idx += 256) ws[idx] = wo[idx];
#pragma unroll
    for (int idx = t; idx < 32 * 96; idx += 256) {
        int n = idx / 96, k = idx - n * 96;
        int gn = node0 + n;
        hs[n * 97 + k] = (gn < N_NODES) ? g_h[gn * HID + k] : 0.f;
    }
    __syncthreads();
    int j = t & 63, nt = t >> 6;
    float acc[8];
#pragma unroll
    for (int nn = 0; nn < 8; nn++) acc[nn] = bo[j];
#pragma unroll 4
    for (int k = 0; k < 96; k++) {
        float w = ws[k * 64 + j];
#pragma unroll
        for (int nn = 0; nn < 8; nn++)
            acc[nn] += hs[(nt + 4 * nn) * 97 + k] * w;
    }
#pragma unroll
    for (int nn = 0; nn < 8; nn++) {
        int gn = node0 + nt + 4 * nn;
        if (gn < N_NODES) out[gn * OUT_DIM + j] = acc[nn];
    }
}

// ---------------- launch ----------------
extern "C" void kernel_launch(void* const* d_in, const int* in_sizes, int n_in,
                              void* d_out, int out_size)
{
    const float* x    = (const float*)d_in[0];
    const int*   ei   = (const int*)d_in[1];
    const float* w_in = (const float*)d_in[2];
    const float* b_in = (const float*)d_in[3];
    const float* tw1  = (const float*)d_in[4];
    const float* tb1  = (const float*)d_in[5];
    const float* tw2  = (const float*)d_in[6];
    const float* tb2  = (const float*)d_in[7];
    const float* wih  = (const float*)d_in[8];
    const float* whh  = (const float*)d_in[9];
    const float* bih  = (const float*)d_in[10];
    const float* bhh  = (const float*)d_in[11];
    const float* wo   = (const float*)d_in[12];
    const float* bo   = (const float*)d_in[13];
    float* out = (float*)d_out;

    const int smem_in  = (128 * 66 + 128 * 16) * 4;                     // 41984 B
    const int smem_gru = (6400 * 2) * 4 + 64 * 4;                       // 51456 B
    cudaFuncSetAttribute(k_input, cudaFuncAttributeMaxDynamicSharedMemorySize, smem_in);
    cudaFuncSetAttribute(k_gru,   cudaFuncAttributeMaxDynamicSharedMemorySize, smem_gru);

    k_initwt<<<(N_NODES + 255) / 256, 256>>>(wih, whh);               // 1
    k_deg<<<(N_EDGES + 255) / 256, 256>>>(ei);                        // 2
    k_scan1<<<SCAN_NB, 1024>>>();                                     // 3
    k_input<<<(N_NODES + 63) / 64, 256, smem_in>>>(x, w_in, b_in,     // 4 (profiled)
                                                   tw1, tb1, tw2, tb2);
    k_scan2<<<1, 64>>>();                                             // 5
    k_scan3<<<SCAN_NB, 1024>>>();                                     // 6 (+order)
    k_csr<<<(N_EDGES + 255) / 256, 256>>>(ei);                        // 7

    for (int it = 0; it < MAX_REC; it++) {
        k_agg<<<(N_NODES + 7) / 8, 256>>>(it);
        k_gru<<<(N_NODES + 63) / 64, 256, smem_gru>>>(bih, bhh, it);
    }
    k_out<<<(N_NODES + 31) / 32, 256>>>(wo, bo, out);
}

// round 9
// speedup vs baseline: 1.0913x; 1.0913x over previous
#include <cuda_runtime.h>
#include <math.h>

#define N_NODES 50000
#define N_EDGES 800000
#define IN_DIM  128
#define HID     96
#define OUT_DIM 64
#define MAX_REC 5
#define SCAN_NB ((N_NODES + 1023) / 1024)   // 49
#define NB_LOOP 148                          // persistent blocks (<= SM count)

typedef unsigned long long u64;

// ---------------- scratch (no allocations allowed) ----------------
__device__ float g_h[N_NODES * HID];
__device__ float g_agg[N_NODES * HID];
__device__ int   g_steps[N_NODES];
__device__ int   g_deg[N_NODES];
__device__ int   g_rowoff[N_NODES + 1];
__device__ int   g_cursor[N_NODES];
__device__ int   g_col[N_EDGES];
__device__ int   g_hist[8];
__device__ int   g_bcur[8];
__device__ int   g_order[N_NODES];
__device__ int   g_cnt[8];
__device__ int   g_bsum[64];
__device__ int   g_boff[64];
__device__ float g_wt_ih[3 * HID * HID];   // [chunk][k][j]
__device__ float g_wt_hh[3 * HID * HID];
__device__ volatile unsigned g_barcnt;

// ---------------- f32x2 helpers ----------------
__device__ __forceinline__ u64 ffma2(u64 a, u64 b, u64 c) {
    u64 d;
    asm("fma.rn.f32x2 %0, %1, %2, %3;" : "=l"(d) : "l"(a), "l"(b), "l"(c));
    return d;
}
__device__ __forceinline__ u64 pack2(float x, float y) {
    u64 r;
    asm("mov.b64 %0, {%1, %2};" : "=l"(r) : "f"(x), "f"(y));
    return r;
}
__device__ __forceinline__ float2 unpack2(u64 v) {
    float2 r;
    asm("mov.b64 {%0, %1}, %2;" : "=f"(r.x), "=f"(r.y) : "l"(v));
    return r;
}
__device__ __forceinline__ float fast_sigmoid(float x) {
    return __fdividef(1.f, 1.f + __expf(-x));
}
__device__ __forceinline__ float fast_tanh(float x) {
    return 1.f - __fdividef(2.f, __expf(2.f * x) + 1.f);
}

// device-wide barrier: monotone counter, all NB_LOOP blocks co-resident
__device__ __forceinline__ void dev_barrier(unsigned target) {
    __syncthreads();
    if (threadIdx.x == 0) {
        __threadfence();                       // release (flushes writes, IVALL)
        atomicAdd((unsigned*)&g_barcnt, 1u);
        while (g_barcnt < target) { }
        __threadfence();                       // acquire (invalidate stale L1)
    }
    __syncthreads();
}

// ---------------- fused init + weight transpose ----------------
__global__ void k_initwt(const float* __restrict__ wih, const float* __restrict__ whh) {
    int i = blockIdx.x * 256 + threadIdx.x;
    if (i == 0) g_barcnt = 0;
    if (i < N_NODES) g_deg[i] = 0;
    if (i < 8) g_hist[i] = 0;
    if (i < 3 * HID * HID) {
        int chunk = i / (HID * HID);
        int r = i - chunk * HID * HID;
        int k = r / HID, j = r - k * HID;
        g_wt_ih[i] = wih[(chunk * HID + j) * HID + k];
        g_wt_hh[i] = whh[(chunk * HID + j) * HID + k];
    }
}

// ---------------- degree histogram ----------------
__global__ void k_deg(const int* __restrict__ ei) {
    int e = blockIdx.x * blockDim.x + threadIdx.x;
    if (e < N_EDGES) atomicAdd(&g_deg[ei[e]], 1);
}

// ---------------- multi-block scan ----------------
__global__ __launch_bounds__(1024) void k_scan1() {
    __shared__ int wsum[32];
    __shared__ int woff[32];
    int t = threadIdx.x, lane = t & 31, wid = t >> 5;
    int i = blockIdx.x * 1024 + t;
    int v = (i < N_NODES) ? g_deg[i] : 0;
    int s = v;
#pragma unroll
    for (int o = 1; o < 32; o <<= 1) {
        int u = __shfl_up_sync(0xffffffffu, s, o);
        if (lane >= o) s += u;
    }
    if (lane == 31) wsum[wid] = s;
    __syncthreads();
    if (wid == 0) {
        int ws = wsum[lane];
        int ss = ws;
#pragma unroll
        for (int o = 1; o < 32; o <<= 1) {
            int u = __shfl_up_sync(0xffffffffu, ss, o);
            if (lane >= o) ss += u;
        }
        woff[lane] = ss - ws;
        if (lane == 31) g_bsum[blockIdx.x] = ss;
    }
    __syncthreads();
    if (i < N_NODES) g_rowoff[i] = s - v + woff[wid];
}

// ---------------- fused input GEMM + relu + tau/steps ----------------
__global__ __launch_bounds__(256) void k_input(
    const float* __restrict__ x, const float* __restrict__ w_in,
    const float* __restrict__ b_in, const float* __restrict__ tw1,
    const float* __restrict__ tb1, const float* __restrict__ tw2,
    const float* __restrict__ tb2)
{
    extern __shared__ float sm_in[];
    float* xs_t = sm_in;               // [128][66]
    float* ts   = xs_t + 128 * 66;     // [128][16]
    int t = threadIdx.x;
    int node0 = blockIdx.x * 64;

#pragma unroll
    for (int idx = t; idx < 128 * 16; idx += 256) ts[idx] = tw1[idx];
#pragma unroll
    for (int idx = t; idx < 64 * 128; idx += 256) {
        int n = idx >> 7, k = idx & 127;
        int gn = node0 + n;
        xs_t[k * 66 + n] = (gn < N_NODES) ? x[gn * IN_DIM + k] : 0.f;
    }
    __syncthreads();

    int cj = t & 31;     // cols {cj, cj+32, cj+64}
    int pg = t >> 5;     // node pairs {pg, pg+8, pg+16, pg+24}

    u64 acc[3][4];
#pragma unroll
    for (int cc = 0; cc < 3; cc++) {
        float b = b_in[cj + 32 * cc];
        u64 bp = pack2(b, b);
#pragma unroll
        for (int q = 0; q < 4; q++) acc[cc][q] = bp;
    }
#pragma unroll 8
    for (int k = 0; k < 128; k++) {
        u64 wd[3];
#pragma unroll
        for (int cc = 0; cc < 3; cc++) {
            float w = __ldg(&w_in[k * 96 + cj + 32 * cc]);
            wd[cc] = pack2(w, w);
        }
        u64 ap[4];
#pragma unroll
        for (int q = 0; q < 4; q++)
            ap[q] = *(const u64*)&xs_t[k * 66 + 2 * (pg + 8 * q)];
#pragma unroll
        for (int cc = 0; cc < 3; cc++)
#pragma unroll
            for (int q = 0; q < 4; q++)
                acc[cc][q] = ffma2(wd[cc], ap[q], acc[cc][q]);
    }
#pragma unroll
    for (int cc = 0; cc < 3; cc++) {
        int col = cj + 32 * cc;
#pragma unroll
        for (int q = 0; q < 4; q++) {
            int n0 = node0 + 2 * (pg + 8 * q);
            float2 g = unpack2(acc[cc][q]);
            if (n0 < N_NODES)     g_h[n0 * HID + col]       = fmaxf(g.x, 0.f);
            if (n0 + 1 < N_NODES) g_h[(n0 + 1) * HID + col] = fmaxf(g.y, 0.f);
        }
    }

    // tau: 4 threads per node
    {
        int tn = t >> 2;
        int tj = t & 3;
        int gn = node0 + tn;
        float hh[4];
#pragma unroll
        for (int u = 0; u < 4; u++) hh[u] = tb1[tj + 4 * u];
#pragma unroll 4
        for (int k = 0; k < 128; k++) {
            float xv = xs_t[k * 66 + tn];
#pragma unroll
            for (int u = 0; u < 4; u++)
                hh[u] += xv * ts[k * 16 + tj + 4 * u];
        }
        float s = 0.f;
#pragma unroll
        for (int u = 0; u < 4; u++)
            s += fmaxf(hh[u], 0.f) * tw2[tj + 4 * u];
        s += __shfl_xor_sync(0xffffffffu, s, 1);
        s += __shfl_xor_sync(0xffffffffu, s, 2);
        if (tj == 0 && gn < N_NODES) {
            s += tb2[0];
            float sp = fmaxf(s, 0.f) + log1pf(expf(-fabsf(s)));
            float inv = 1.0f / sp;
            int st = (inv >= (float)MAX_REC) ? MAX_REC : (int)inv;
            g_steps[gn] = st;
            atomicAdd(&g_hist[st], 1);
        }
    }
}

__global__ void k_scan2() {
    __shared__ int sh[64];
    int t = threadIdx.x;
    sh[t] = (t < SCAN_NB) ? g_bsum[t] : 0;
    __syncthreads();
    if (t == 0) {
        int run = 0;
        for (int b = 0; b < SCAN_NB; b++) { g_boff[b] = run; run += sh[b]; }
        g_rowoff[N_NODES] = run;
        int suffix = 0;
        int start[6];
        for (int s = 5; s >= 0; s--) { start[s] = suffix; suffix += g_hist[s]; }
        for (int s = 0; s < 6; s++) g_bcur[s] = start[s];
        for (int it = 0; it < 5; it++) g_cnt[it] = start[it];
    }
}

// scan3 + order fused
__global__ __launch_bounds__(1024) void k_scan3() {
    int i = blockIdx.x * 1024 + threadIdx.x;
    if (i < N_NODES) {
        int v = g_rowoff[i] + g_boff[blockIdx.x];
        g_rowoff[i] = v;
        g_cursor[i] = v;
        int s = g_steps[i];
        int pos = atomicAdd(&g_bcur[s], 1);
        g_order[pos] = i;
    }
}

// ---------------- CSR fill ----------------
__global__ void k_csr(const int* __restrict__ ei) {
    int e = blockIdx.x * blockDim.x + threadIdx.x;
    if (e < N_EDGES) {
        int r = ei[e];
        int c = ei[N_EDGES + e];
        int pos = atomicAdd(&g_cursor[r], 1);
        g_col[pos] = c;
    }
}

// ---------------- persistent fused loop: 5 x (agg ; barrier ; gru ; barrier) --
// NB_LOOP blocks x 256 threads, 198.9KB smem -> 1 block/SM, all co-resident.
__global__ __launch_bounds__(256, 1) void k_loop(
    const float* __restrict__ bih, const float* __restrict__ bhh)
{
    extern __shared__ float sm_g[];
    float* agg_s = sm_g;                 // 6400
    float* h_s   = agg_s + 6400;         // 6400
    float* w0a   = h_s + 6400;           // 9216 (ih, gate A)
    float* w0b   = w0a + 9216;           // 9216 (hh, gate A)
    float* w1a   = w0b + 9216;           // 9216 (ih, gate B)
    float* w1b   = w1a + 9216;           // 9216 (hh, gate B)
    int* nodes_s = (int*)(w1b + 9216);

    int t = threadIdx.x;
    int bid = blockIdx.x;
    unsigned gen = 0;

#pragma unroll 1
    for (int it = 0; it < MAX_REC; it++) {
        int cnt = g_cnt[it];

        // ---- phase A: aggregation (warp per node, grid-stride) ----
        {
            int wid = t >> 5, lane = t & 31;
            int grp = lane >> 2;
            int l4  = lane & 3;
#pragma unroll 1
            for (int w = bid * 8 + wid; w < cnt; w += NB_LOOP * 8) {
                int node = g_order[w];
                int base = g_rowoff[node], end = g_rowoff[node + 1];
                const float4* hi4 = (const float4*)(g_h + node * HID);
                float4 hi[6], acc[6];
#pragma unroll
                for (int u = 0; u < 6; u++) {
                    hi[u] = hi4[l4 + 4 * u];
                    acc[u] = make_float4(0.f, 0.f, 0.f, 0.f);
                }
#pragma unroll 4
                for (int e = base + grp; e < end; e += 8) {
                    int cc = __ldg(&g_col[e]);
                    const float4* hp = (const float4*)(g_h + cc * HID);
#pragma unroll
                    for (int u = 0; u < 6; u++) {
                        float4 v = hp[l4 + 4 * u];
                        acc[u].x += fabsf(v.x - hi[u].x);
                        acc[u].y += fabsf(v.y - hi[u].y);
                        acc[u].z += fabsf(v.z - hi[u].z);
                        acc[u].w += fabsf(v.w - hi[u].w);
                    }
                }
#pragma unroll
                for (int off = 4; off < 32; off <<= 1) {
#pragma unroll
                    for (int u = 0; u < 6; u++) {
                        acc[u].x += __shfl_xor_sync(0xffffffffu, acc[u].x, off);
                        acc[u].y += __shfl_xor_sync(0xffffffffu, acc[u].y, off);
                        acc[u].z += __shfl_xor_sync(0xffffffffu, acc[u].z, off);
                        acc[u].w += __shfl_xor_sync(0xffffffffu, acc[u].w, off);
                    }
                }
                if (grp == 0) {
                    float4* ar = (float4*)(g_agg + (long long)node * HID);
#pragma unroll
                    for (int u = 0; u < 6; u++) ar[l4 + 4 * u] = acc[u];
                }
            }
        }
        gen++;
        dev_barrier(NB_LOOP * gen);

        // ---- phase B: GRU tiles (R7 math, grid-stride) ----
#pragma unroll 1
        for (int tile = bid; tile * 64 < cnt; tile += NB_LOOP) {
            int tile0 = tile * 64;
            int nvalid = min(64, cnt - tile0);

            if (t < 64) nodes_s[t] = g_order[tile0 + min(t, nvalid - 1)];
            __syncthreads();
#pragma unroll
            for (int idx = t; idx < 64 * 24; idx += 256) {
                int n = idx / 24, c4 = idx - n * 24;
                int gn = nodes_s[n];
                ((float4*)(agg_s + n * 100))[c4] = ((const float4*)(g_agg + gn * HID))[c4];
                ((float4*)(h_s + n * 100))[c4]   = ((const float4*)(g_h + gn * HID))[c4];
            }
#pragma unroll
            for (int idx = t; idx < 2304; idx += 256) {
                ((float4*)w0a)[idx] = ((const float4*)g_wt_ih)[idx];
                ((float4*)w0b)[idx] = ((const float4*)g_wt_hh)[idx];
                ((float4*)w1a)[idx] = ((const float4*)(g_wt_ih + 9216))[idx];
                ((float4*)w1b)[idx] = ((const float4*)(g_wt_hh + 9216))[idx];
            }
            __syncthreads();

            int cp = t & 15;
            int ng = t >> 4;
            int nb = 4 * ng;

            u64 accR[3][4], accZ[3][4];
#pragma unroll
            for (int cc = 0; cc < 3; cc++) {
                int c2 = 2 * (cp + 16 * cc);
                float2 bi0 = *(const float2*)&bih[c2];
                float2 bh0 = *(const float2*)&bhh[c2];
                float2 bi1 = *(const float2*)&bih[96 + c2];
                float2 bh1 = *(const float2*)&bhh[96 + c2];
                u64 bR = pack2(bi0.x + bh0.x, bi0.y + bh0.y);
                u64 bZ = pack2(bi1.x + bh1.x, bi1.y + bh1.y);
#pragma unroll
                for (int q = 0; q < 4; q++) { accR[cc][q] = bR; accZ[cc][q] = bZ; }
            }
#pragma unroll 4
            for (int k = 0; k < 96; k++) {
                u64 wra[3], wrb[3], wza[3], wzb[3];
#pragma unroll
                for (int cc = 0; cc < 3; cc++) {
                    int o = k * 96 + 2 * (cp + 16 * cc);
                    wra[cc] = *(const u64*)&w0a[o];
                    wrb[cc] = *(const u64*)&w0b[o];
                    wza[cc] = *(const u64*)&w1a[o];
                    wzb[cc] = *(const u64*)&w1b[o];
                }
                u64 a2[4], h2[4];
#pragma unroll
                for (int q = 0; q < 4; q++) {
                    float a  = agg_s[(nb + q) * 100 + k];
                    float hv = h_s[(nb + q) * 100 + k];
                    a2[q] = pack2(a, a);
                    h2[q] = pack2(hv, hv);
                }
#pragma unroll
                for (int cc = 0; cc < 3; cc++)
#pragma unroll
                    for (int q = 0; q < 4; q++) {
                        accR[cc][q] = ffma2(wra[cc], a2[q], accR[cc][q]);
                        accR[cc][q] = ffma2(wrb[cc], h2[q], accR[cc][q]);
                        accZ[cc][q] = ffma2(wza[cc], a2[q], accZ[cc][q]);
                        accZ[cc][q] = ffma2(wzb[cc], h2[q], accZ[cc][q]);
                    }
            }
            u64 r_g[3][4], z_g[3][4];
#pragma unroll
            for (int cc = 0; cc < 3; cc++)
#pragma unroll
                for (int q = 0; q < 4; q++) {
                    float2 gr = unpack2(accR[cc][q]);
                    float2 gz = unpack2(accZ[cc][q]);
                    r_g[cc][q] = pack2(fast_sigmoid(gr.x), fast_sigmoid(gr.y));
                    z_g[cc][q] = pack2(fast_sigmoid(gz.x), fast_sigmoid(gz.y));
                }

            __syncthreads();
#pragma unroll
            for (int idx = t; idx < 2304; idx += 256) {
                ((float4*)w0a)[idx] = ((const float4*)(g_wt_ih + 18432))[idx];
                ((float4*)w0b)[idx] = ((const float4*)(g_wt_hh + 18432))[idx];
            }
            __syncthreads();

            u64 ai[3][4], ah[3][4];
#pragma unroll
            for (int cc = 0; cc < 3; cc++) {
                int c2 = 2 * (cp + 16 * cc);
                float2 b1 = *(const float2*)&bih[192 + c2];
                float2 b2 = *(const float2*)&bhh[192 + c2];
                u64 p1 = pack2(b1.x, b1.y), p2 = pack2(b2.x, b2.y);
#pragma unroll
                for (int q = 0; q < 4; q++) { ai[cc][q] = p1; ah[cc][q] = p2; }
            }
#pragma unroll 4
            for (int k = 0; k < 96; k++) {
                u64 wa[3], wb[3];
#pragma unroll
                for (int cc = 0; cc < 3; cc++) {
                    int o = k * 96 + 2 * (cp + 16 * cc);
                    wa[cc] = *(const u64*)&w0a[o];
                    wb[cc] = *(const u64*)&w0b[o];
                }
                u64 a2[4], h2[4];
#pragma unroll
                for (int q = 0; q < 4; q++) {
                    float a  = agg_s[(nb + q) * 100 + k];
                    float hv = h_s[(nb + q) * 100 + k];
                    a2[q] = pack2(a, a);
                    h2[q] = pack2(hv, hv);
                }
#pragma unroll
                for (int cc = 0; cc < 3; cc++)
#pragma unroll
                    for (int q = 0; q < 4; q++) {
                        ai[cc][q] = ffma2(wa[cc], a2[q], ai[cc][q]);
                        ah[cc][q] = ffma2(wb[cc], h2[q], ah[cc][q]);
                    }
            }
#pragma unroll
            for (int cc = 0; cc < 3; cc++) {
                int c2 = 2 * (cp + 16 * cc);
#pragma unroll
                for (int q = 0; q < 4; q++) {
                    int n = nb + q;
                    float2 vi = unpack2(ai[cc][q]);
                    float2 vh = unpack2(ah[cc][q]);
                    float2 rr = unpack2(r_g[cc][q]);
                    float2 zz = unpack2(z_g[cc][q]);
                    float hold0 = h_s[n * 100 + c2];
                    float hold1 = h_s[n * 100 + c2 + 1];
                    float nv0 = fast_tanh(vi.x + rr.x * vh.x);
                    float nv1 = fast_tanh(vi.y + rr.y * vh.y);
                    float h0 = (1.f - zz.x) * nv0 + zz.x * hold0;
                    float h1 = (1.f - zz.y) * nv1 + zz.y * hold1;
                    *(float2*)&g_h[nodes_s[n] * HID + c2] = make_float2(h0, h1);
                }
            }
            __syncthreads();   // nodes_s/smem reuse safety before next tile
        }
        gen++;
        dev_barrier(NB_LOOP * gen);
    }
}

// ---------------- output GEMM ----------------
__global__ __launch_bounds__(256) void k_out(
    const float* __restrict__ wo, const float* __restrict__ bo,
    float* __restrict__ out)
{
    __shared__ float ws[96 * 64];
    __shared__ float hs[32 * 97];
    int t = threadIdx.x;
    int node0 = blockIdx.x * 32;
#pragma unroll
    for (int idx = t; idx < 96 * 64; idx += 256) ws[idx] = wo[idx];
#pragma unroll
    for (int idx = t; idx < 32 * 96; idx += 256) {
        int n = idx / 96, k = idx - n * 96;
        int gn = node0 + n;
        hs[n * 97 + k] = (gn < N_NODES) ? g_h[gn * HID + k] : 0.f;
    }
    __syncthreads();
    int j = t & 63, nt = t >> 6;
    float acc[8];
#pragma unroll
    for (int nn = 0; nn < 8; nn++) acc[nn] = bo[j];
#pragma unroll 4
    for (int k = 0; k < 96; k++) {
        float w = ws[k * 64 + j];
#pragma unroll
        for (int nn = 0; nn < 8; nn++)
            acc[nn] += hs[(nt + 4 * nn) * 97 + k] * w;
    }
#pragma unroll
    for (int nn = 0; nn < 8; nn++) {
        int gn = node0 + nt + 4 * nn;
        if (gn < N_NODES) out[gn * OUT_DIM + j] = acc[nn];
    }
}

// ---------------- launch ----------------
extern "C" void kernel_launch(void* const* d_in, const int* in_sizes, int n_in,
                              void* d_out, int out_size)
{
    const float* x    = (const float*)d_in[0];
    const int*   ei   = (const int*)d_in[1];
    const float* w_in = (const float*)d_in[2];
    const float* b_in = (const float*)d_in[3];
    const float* tw1  = (const float*)d_in[4];
    const float* tb1  = (const float*)d_in[5];
    const float* tw2  = (const float*)d_in[6];
    const float* tb2  = (const float*)d_in[7];
    const float* wih  = (const float*)d_in[8];
    const float* whh  = (const float*)d_in[9];
    const float* bih  = (const float*)d_in[10];
    const float* bhh  = (const float*)d_in[11];
    const float* wo   = (const float*)d_in[12];
    const float* bo   = (const float*)d_in[13];
    float* out = (float*)d_out;

    const int smem_in   = (128 * 66 + 128 * 16) * 4;                 // 41984 B
    const int smem_loop = (6400 * 2 + 9216 * 4) * 4 + 64 * 4;        // 198912 B
    cudaFuncSetAttribute(k_input, cudaFuncAttributeMaxDynamicSharedMemorySize, smem_in);
    cudaFuncSetAttribute(k_loop,  cudaFuncAttributeMaxDynamicSharedMemorySize, smem_loop);

    k_initwt<<<(N_NODES + 255) / 256, 256>>>(wih, whh);               // 1
    k_deg<<<(N_EDGES + 255) / 256, 256>>>(ei);                        // 2
    k_scan1<<<SCAN_NB, 1024>>>();                                     // 3
    k_input<<<(N_NODES + 63) / 64, 256, smem_in>>>(x, w_in, b_in,     // 4 (profiled)
                                                   tw1, tb1, tw2, tb2);
    k_scan2<<<1, 64>>>();                                             // 5
    k_scan3<<<SCAN_NB, 1024>>>();                                     // 6 (+order)
    k_csr<<<(N_EDGES + 255) / 256, 256>>>(ei);                        // 7

    k_loop<<<NB_LOOP, 256, smem_loop>>>(bih, bhh);                    // 8 (all 5 iters)

    k_out<<<(N_NODES + 31) / 32, 256>>>(wo, bo, out);                 // 9
}

// round 10
// speedup vs baseline: 1.1340x; 1.0391x over previous
#include <cuda_runtime.h>
#include <math.h>

#define N_NODES 50000
#define N_EDGES 800000
#define IN_DIM  128
#define HID     96
#define OUT_DIM 64
#define MAX_REC 5
#define SCAN_NB ((N_NODES + 1023) / 1024)   // 49

typedef unsigned long long u64;

// ---------------- scratch (no allocations allowed) ----------------
__device__ float g_h[N_NODES * HID];
__device__ float g_agg[N_NODES * HID];
__device__ int   g_steps[N_NODES];
__device__ int   g_deg[N_NODES];
__device__ int   g_rowoff[N_NODES + 1];
__device__ int   g_cursor[N_NODES];
__device__ int   g_col[N_EDGES];
__device__ int   g_hist[8];
__device__ int   g_bcur[8];
__device__ int   g_order[N_NODES];
__device__ int   g_cnt[8];
__device__ int   g_bsum[64];
__device__ int   g_boff[64];
__device__ float g_wt_ih[3 * HID * HID];   // [chunk][k][j]
__device__ float g_wt_hh[3 * HID * HID];

// ---------------- f32x2 helpers ----------------
__device__ __forceinline__ u64 ffma2(u64 a, u64 b, u64 c) {
    u64 d;
    asm("fma.rn.f32x2 %0, %1, %2, %3;" : "=l"(d) : "l"(a), "l"(b), "l"(c));
    return d;
}
__device__ __forceinline__ u64 pack2(float x, float y) {
    u64 r;
    asm("mov.b64 %0, {%1, %2};" : "=l"(r) : "f"(x), "f"(y));
    return r;
}
__device__ __forceinline__ float2 unpack2(u64 v) {
    float2 r;
    asm("mov.b64 {%0, %1}, %2;" : "=f"(r.x), "=f"(r.y) : "l"(v));
    return r;
}
__device__ __forceinline__ float fast_sigmoid(float x) {
    return __fdividef(1.f, 1.f + __expf(-x));
}
__device__ __forceinline__ float fast_tanh(float x) {
    return 1.f - __fdividef(2.f, __expf(2.f * x) + 1.f);
}

// ---------------- fused init + weight transpose ----------------
__global__ void k_initwt(const float* __restrict__ wih, const float* __restrict__ whh) {
    int i = blockIdx.x * 256 + threadIdx.x;
    if (i < N_NODES) g_deg[i] = 0;
    if (i < 8) g_hist[i] = 0;
    if (i < 3 * HID * HID) {
        int chunk = i / (HID * HID);
        int r = i - chunk * HID * HID;
        int k = r / HID, j = r - k * HID;
        g_wt_ih[i] = wih[(chunk * HID + j) * HID + k];
        g_wt_hh[i] = whh[(chunk * HID + j) * HID + k];
    }
}

// ---------------- degree histogram ----------------
__global__ void k_deg(const int* __restrict__ ei) {
    int e = blockIdx.x * blockDim.x + threadIdx.x;
    if (e < N_EDGES) atomicAdd(&g_deg[ei[e]], 1);
}

// ---------------- multi-block scan ----------------
__global__ __launch_bounds__(1024) void k_scan1() {
    __shared__ int wsum[32];
    __shared__ int woff[32];
    int t = threadIdx.x, lane = t & 31, wid = t >> 5;
    int i = blockIdx.x * 1024 + t;
    int v = (i < N_NODES) ? g_deg[i] : 0;
    int s = v;
#pragma unroll
    for (int o = 1; o < 32; o <<= 1) {
        int u = __shfl_up_sync(0xffffffffu, s, o);
        if (lane >= o) s += u;
    }
    if (lane == 31) wsum[wid] = s;
    __syncthreads();
    if (wid == 0) {
        int ws = wsum[lane];
        int ss = ws;
#pragma unroll
        for (int o = 1; o < 32; o <<= 1) {
            int u = __shfl_up_sync(0xffffffffu, ss, o);
            if (lane >= o) ss += u;
        }
        woff[lane] = ss - ws;
        if (lane == 31) g_bsum[blockIdx.x] = ss;
    }
    __syncthreads();
    if (i < N_NODES) g_rowoff[i] = s - v + woff[wid];
}

// ---------------- fused input GEMM + relu + tau/steps ----------------
__global__ __launch_bounds__(256, 5) void k_input(
    const float* __restrict__ x, const float* __restrict__ w_in,
    const float* __restrict__ b_in, const float* __restrict__ tw1,
    const float* __restrict__ tb1, const float* __restrict__ tw2,
    const float* __restrict__ tb2)
{
    extern __shared__ float sm_in[];
    float* xs_t = sm_in;               // [128][66]
    float* ts   = xs_t + 128 * 66;     // [128][16]
    int t = threadIdx.x;
    int node0 = blockIdx.x * 64;

#pragma unroll
    for (int idx = t; idx < 128 * 16; idx += 256) ts[idx] = tw1[idx];
#pragma unroll
    for (int idx = t; idx < 64 * 128; idx += 256) {
        int n = idx >> 7, k = idx & 127;
        int gn = node0 + n;
        xs_t[k * 66 + n] = (gn < N_NODES) ? x[gn * IN_DIM + k] : 0.f;
    }
    __syncthreads();

    int cj = t & 31;     // cols {cj, cj+32, cj+64}
    int pg = t >> 5;     // node pairs {pg, pg+8, pg+16, pg+24}

    u64 acc[3][4];
#pragma unroll
    for (int cc = 0; cc < 3; cc++) {
        float b = b_in[cj + 32 * cc];
        u64 bp = pack2(b, b);
#pragma unroll
        for (int q = 0; q < 4; q++) acc[cc][q] = bp;
    }
#pragma unroll 8
    for (int k = 0; k < 128; k++) {
        u64 wd[3];
#pragma unroll
        for (int cc = 0; cc < 3; cc++) {
            float w = __ldg(&w_in[k * 96 + cj + 32 * cc]);
            wd[cc] = pack2(w, w);
        }
        u64 ap[4];
#pragma unroll
        for (int q = 0; q < 4; q++)
            ap[q] = *(const u64*)&xs_t[k * 66 + 2 * (pg + 8 * q)];
#pragma unroll
        for (int cc = 0; cc < 3; cc++)
#pragma unroll
            for (int q = 0; q < 4; q++)
                acc[cc][q] = ffma2(wd[cc], ap[q], acc[cc][q]);
    }
#pragma unroll
    for (int cc = 0; cc < 3; cc++) {
        int col = cj + 32 * cc;
#pragma unroll
        for (int q = 0; q < 4; q++) {
            int n0 = node0 + 2 * (pg + 8 * q);
            float2 g = unpack2(acc[cc][q]);
            if (n0 < N_NODES)     g_h[n0 * HID + col]       = fmaxf(g.x, 0.f);
            if (n0 + 1 < N_NODES) g_h[(n0 + 1) * HID + col] = fmaxf(g.y, 0.f);
        }
    }

    // tau: 4 threads per node
    {
        int tn = t >> 2;
        int tj = t & 3;
        int gn = node0 + tn;
        float hh[4];
#pragma unroll
        for (int u = 0; u < 4; u++) hh[u] = tb1[tj + 4 * u];
#pragma unroll 4
        for (int k = 0; k < 128; k++) {
            float xv = xs_t[k * 66 + tn];
#pragma unroll
            for (int u = 0; u < 4; u++)
                hh[u] += xv * ts[k * 16 + tj + 4 * u];
        }
        float s = 0.f;
#pragma unroll
        for (int u = 0; u < 4; u++)
            s += fmaxf(hh[u], 0.f) * tw2[tj + 4 * u];
        s += __shfl_xor_sync(0xffffffffu, s, 1);
        s += __shfl_xor_sync(0xffffffffu, s, 2);
        if (tj == 0 && gn < N_NODES) {
            s += tb2[0];
            float sp = fmaxf(s, 0.f) + log1pf(expf(-fabsf(s)));
            float inv = 1.0f / sp;
            int st = (inv >= (float)MAX_REC) ? MAX_REC : (int)inv;
            g_steps[gn] = st;
            atomicAdd(&g_hist[st], 1);
        }
    }
}

__global__ void k_scan2() {
    __shared__ int sh[64];
    int t = threadIdx.x;
    sh[t] = (t < SCAN_NB) ? g_bsum[t] : 0;
    __syncthreads();
    if (t == 0) {
        int run = 0;
        for (int b = 0; b < SCAN_NB; b++) { g_boff[b] = run; run += sh[b]; }
        g_rowoff[N_NODES] = run;
        int suffix = 0;
        int start[6];
        for (int s = 5; s >= 0; s--) { start[s] = suffix; suffix += g_hist[s]; }
        for (int s = 0; s < 6; s++) g_bcur[s] = start[s];
        for (int it = 0; it < 5; it++) g_cnt[it] = start[it];
    }
}

// scan3 + order fused
__global__ __launch_bounds__(1024) void k_scan3() {
    int i = blockIdx.x * 1024 + threadIdx.x;
    if (i < N_NODES) {
        int v = g_rowoff[i] + g_boff[blockIdx.x];
        g_rowoff[i] = v;
        g_cursor[i] = v;
        int s = g_steps[i];
        int pos = atomicAdd(&g_bcur[s], 1);
        g_order[pos] = i;
    }
}

// ---------------- CSR fill ----------------
__global__ void k_csr(const int* __restrict__ ei) {
    int e = blockIdx.x * blockDim.x + threadIdx.x;
    if (e < N_EDGES) {
        int r = ei[e];
        int c = ei[N_EDGES + e];
        int pos = atomicAdd(&g_cursor[r], 1);
        g_col[pos] = c;
    }
}

// ---------------- edge aggregation v3: 2 warps per node (half-row each) ------
// block = 256 threads = 8 warps = 4 nodes. Warp parity p owns float4 slots
// {l4 + 4u + 12p : u in [0,3)}. 8 edge-groups of 4 lanes per warp.
__global__ __launch_bounds__(256) void k_agg(int it) {
    int wid = threadIdx.x >> 5;
    int w = blockIdx.x * 4 + (wid >> 1);
    if (w >= g_cnt[it]) return;
    int p = wid & 1;
    int node = g_order[w];
    int lane = threadIdx.x & 31;
    int grp = lane >> 2;       // 8 edge subgroups of 4 lanes
    int l4  = lane & 3;
    int base = g_rowoff[node], end = g_rowoff[node + 1];

    const float4* hi4 = (const float4*)(g_h + node * HID);
    float4 hi[3], acc[3];
#pragma unroll
    for (int u = 0; u < 3; u++) {
        hi[u] = hi4[l4 + 4 * u + 12 * p];
        acc[u] = make_float4(0.f, 0.f, 0.f, 0.f);
    }

#pragma unroll 4
    for (int e = base + grp; e < end; e += 8) {
        int cc = __ldg(&g_col[e]);
        const float4* hp = (const float4*)(g_h + cc * HID);
#pragma unroll
        for (int u = 0; u < 3; u++) {
            float4 v = hp[l4 + 4 * u + 12 * p];
            acc[u].x += fabsf(v.x - hi[u].x);
            acc[u].y += fabsf(v.y - hi[u].y);
            acc[u].z += fabsf(v.z - hi[u].z);
            acc[u].w += fabsf(v.w - hi[u].w);
        }
    }
#pragma unroll
    for (int off = 4; off < 32; off <<= 1) {
#pragma unroll
        for (int u = 0; u < 3; u++) {
            acc[u].x += __shfl_xor_sync(0xffffffffu, acc[u].x, off);
            acc[u].y += __shfl_xor_sync(0xffffffffu, acc[u].y, off);
            acc[u].z += __shfl_xor_sync(0xffffffffu, acc[u].z, off);
            acc[u].w += __shfl_xor_sync(0xffffffffu, acc[u].w, off);
        }
    }
    if (grp == 0) {
        float4* ar = (float4*)(g_agg + (long long)node * HID);
#pragma unroll
        for (int u = 0; u < 3; u++) ar[l4 + 4 * u + 12 * p] = acc[u];
    }
}

// ---------------- GRU v3 (R7 exact): smem weights, f32x2, fast activations ---
__global__ __launch_bounds__(256, 1) void k_gru(
    const float* __restrict__ bih, const float* __restrict__ bhh, int it)
{
    extern __shared__ float sm_g[];
    float* agg_s = sm_g;                 // 6400
    float* h_s   = agg_s + 6400;         // 6400
    float* w0a   = h_s + 6400;           // 9216 (r: ih)
    float* w0b   = w0a + 9216;           // 9216 (r: hh)
    float* w1a   = w0b + 9216;           // 9216 (z: ih)
    float* w1b   = w1a + 9216;           // 9216 (z: hh)
    int* nodes_s = (int*)(w1b + 9216);

    int t = threadIdx.x;
    int cnt = g_cnt[it];
    int tile0 = blockIdx.x * 64;
    if (tile0 >= cnt) return;
    int nvalid = min(64, cnt - tile0);

    if (t < 64) nodes_s[t] = g_order[tile0 + min(t, nvalid - 1)];
    __syncthreads();
#pragma unroll
    for (int idx = t; idx < 64 * 24; idx += 256) {
        int n = idx / 24, c4 = idx - n * 24;
        int gn = nodes_s[n];
        ((float4*)(agg_s + n * 100))[c4] = ((const float4*)(g_agg + gn * HID))[c4];
        ((float4*)(h_s + n * 100))[c4]   = ((const float4*)(g_h + gn * HID))[c4];
    }
#pragma unroll
    for (int idx = t; idx < 2304; idx += 256) {
        ((float4*)w0a)[idx] = ((const float4*)g_wt_ih)[idx];
        ((float4*)w0b)[idx] = ((const float4*)g_wt_hh)[idx];
        ((float4*)w1a)[idx] = ((const float4*)(g_wt_ih + 9216))[idx];
        ((float4*)w1b)[idx] = ((const float4*)(g_wt_hh + 9216))[idx];
    }
    __syncthreads();

    int cp = t & 15;     // col-pairs {cp, cp+16, cp+32} (cols 2p, 2p+1)
    int ng = t >> 4;     // nodes 4ng..4ng+3
    int nb = 4 * ng;

    u64 accR[3][4], accZ[3][4];
#pragma unroll
    for (int cc = 0; cc < 3; cc++) {
        int c2 = 2 * (cp + 16 * cc);
        float2 bi0 = *(const float2*)&bih[c2];
        float2 bh0 = *(const float2*)&bhh[c2];
        float2 bi1 = *(const float2*)&bih[96 + c2];
        float2 bh1 = *(const float2*)&bhh[96 + c2];
        u64 bR = pack2(bi0.x + bh0.x, bi0.y + bh0.y);
        u64 bZ = pack2(bi1.x + bh1.x, bi1.y + bh1.y);
#pragma unroll
        for (int q = 0; q < 4; q++) { accR[cc][q] = bR; accZ[cc][q] = bZ; }
    }
#pragma unroll 4
    for (int k = 0; k < 96; k++) {
        u64 wra[3], wrb[3], wza[3], wzb[3];
#pragma unroll
        for (int cc = 0; cc < 3; cc++) {
            int o = k * 96 + 2 * (cp + 16 * cc);
            wra[cc] = *(const u64*)&w0a[o];
            wrb[cc] = *(const u64*)&w0b[o];
            wza[cc] = *(const u64*)&w1a[o];
            wzb[cc] = *(const u64*)&w1b[o];
        }
        u64 a2[4], h2[4];
#pragma unroll
        for (int q = 0; q < 4; q++) {
            float a  = agg_s[(nb + q) * 100 + k];
            float hv = h_s[(nb + q) * 100 + k];
            a2[q] = pack2(a, a);
            h2[q] = pack2(hv, hv);
        }
#pragma unroll
        for (int cc = 0; cc < 3; cc++)
#pragma unroll
            for (int q = 0; q < 4; q++) {
                accR[cc][q] = ffma2(wra[cc], a2[q], accR[cc][q]);
                accR[cc][q] = ffma2(wrb[cc], h2[q], accR[cc][q]);
                accZ[cc][q] = ffma2(wza[cc], a2[q], accZ[cc][q]);
                accZ[cc][q] = ffma2(wzb[cc], h2[q], accZ[cc][q]);
            }
    }
    u64 r_g[3][4], z_g[3][4];
#pragma unroll
    for (int cc = 0; cc < 3; cc++)
#pragma unroll
        for (int q = 0; q < 4; q++) {
            float2 gr = unpack2(accR[cc][q]);
            float2 gz = unpack2(accZ[cc][q]);
            r_g[cc][q] = pack2(fast_sigmoid(gr.x), fast_sigmoid(gr.y));
            z_g[cc][q] = pack2(fast_sigmoid(gz.x), fast_sigmoid(gz.y));
        }

    // chunk 2: candidate gate
    __syncthreads();
#pragma unroll
    for (int idx = t; idx < 2304; idx += 256) {
        ((float4*)w0a)[idx] = ((const float4*)(g_wt_ih + 18432))[idx];
        ((float4*)w0b)[idx] = ((const float4*)(g_wt_hh + 18432))[idx];
    }
    __syncthreads();

    u64 ai[3][4], ah[3][4];
#pragma unroll
    for (int cc = 0; cc < 3; cc++) {
        int c2 = 2 * (cp + 16 * cc);
        float2 b1 = *(const float2*)&bih[192 + c2];
        float2 b2 = *(const float2*)&bhh[192 + c2];
        u64 p1 = pack2(b1.x, b1.y), p2 = pack2(b2.x, b2.y);
#pragma unroll
        for (int q = 0; q < 4; q++) { ai[cc][q] = p1; ah[cc][q] = p2; }
    }
#pragma unroll 4
    for (int k = 0; k < 96; k++) {
        u64 wa[3], wb[3];
#pragma unroll
        for (int cc = 0; cc < 3; cc++) {
            int o = k * 96 + 2 * (cp + 16 * cc);
            wa[cc] = *(const u64*)&w0a[o];
            wb[cc] = *(const u64*)&w0b[o];
        }
        u64 a2[4], h2[4];
#pragma unroll
        for (int q = 0; q < 4; q++) {
            float a  = agg_s[(nb + q) * 100 + k];
            float hv = h_s[(nb + q) * 100 + k];
            a2[q] = pack2(a, a);
            h2[q] = pack2(hv, hv);
        }
#pragma unroll
        for (int cc = 0; cc < 3; cc++)
#pragma unroll
            for (int q = 0; q < 4; q++) {
                ai[cc][q] = ffma2(wa[cc], a2[q], ai[cc][q]);
                ah[cc][q] = ffma2(wb[cc], h2[q], ah[cc][q]);
            }
    }
#pragma unroll
    for (int cc = 0; cc < 3; cc++) {
        int c2 = 2 * (cp + 16 * cc);
#pragma unroll
        for (int q = 0; q < 4; q++) {
            int n = nb + q;
            float2 vi = unpack2(ai[cc][q]);
            float2 vh = unpack2(ah[cc][q]);
            float2 rr = unpack2(r_g[cc][q]);
            float2 zz = unpack2(z_g[cc][q]);
            float hold0 = h_s[n * 100 + c2];
            float hold1 = h_s[n * 100 + c2 + 1];
            float nv0 = fast_tanh(vi.x + rr.x * vh.x);
            float nv1 = fast_tanh(vi.y + rr.y * vh.y);
            float h0 = (1.f - zz.x) * nv0 + zz.x * hold0;
            float h1 = (1.f - zz.y) * nv1 + zz.y * hold1;
            *(float2*)&g_h[nodes_s[n] * HID + c2] = make_float2(h0, h1);
        }
    }
}

// ---------------- output GEMM ----------------
__global__ __launch_bounds__(256) void k_out(
    const float* __restrict__ wo, const float* __restrict__ bo,
    float* __restrict__ out)
{
    __shared__ float ws[96 * 64];
    __shared__ float hs[32 * 97];
    int t = threadIdx.x;
    int node0 = blockIdx.x * 32;
#pragma unroll
    for (int idx = t; idx < 96 * 64; idx += 256) ws[idx] = wo[idx];
#pragma unroll
    for (int idx = t; idx < 32 * 96; idx += 256) {
        int n = idx / 96, k = idx - n * 96;
        int gn = node0 + n;
        hs[n * 97 + k] = (gn < N_NODES) ? g_h[gn * HID + k] : 0.f;
    }
    __syncthreads();
    int j = t & 63, nt = t >> 6;
    float acc[8];
#pragma unroll
    for (int nn = 0; nn < 8; nn++) acc[nn] = bo[j];
#pragma unroll 4
    for (int k = 0; k < 96; k++) {
        float w = ws[k * 64 + j];
#pragma unroll
        for (int nn = 0; nn < 8; nn++)
            acc[nn] += hs[(nt + 4 * nn) * 97 + k] * w;
    }
#pragma unroll
    for (int nn = 0; nn < 8; nn++) {
        int gn = node0 + nt + 4 * nn;
        if (gn < N_NODES) out[gn * OUT_DIM + j] = acc[nn];
    }
}

// ---------------- launch ----------------
extern "C" void kernel_launch(void* const* d_in, const int* in_sizes, int n_in,
                              void* d_out, int out_size)
{
    const float* x    = (const float*)d_in[0];
    const int*   ei   = (const int*)d_in[1];
    const float* w_in = (const float*)d_in[2];
    const float* b_in = (const float*)d_in[3];
    const float* tw1  = (const float*)d_in[4];
    const float* tb1  = (const float*)d_in[5];
    const float* tw2  = (const float*)d_in[6];
    const float* tb2  = (const float*)d_in[7];
    const float* wih  = (const float*)d_in[8];
    const float* whh  = (const float*)d_in[9];
    const float* bih  = (const float*)d_in[10];
    const float* bhh  = (const float*)d_in[11];
    const float* wo   = (const float*)d_in[12];
    const float* bo   = (const float*)d_in[13];
    float* out = (float*)d_out;

    const int smem_in  = (128 * 66 + 128 * 16) * 4;                     // 41984 B
    const int smem_gru = (6400 * 2 + 9216 * 4) * 4 + 64 * 4;            // 198912 B
    cudaFuncSetAttribute(k_input, cudaFuncAttributeMaxDynamicSharedMemorySize, smem_in);
    cudaFuncSetAttribute(k_gru,   cudaFuncAttributeMaxDynamicSharedMemorySize, smem_gru);

    k_initwt<<<(N_NODES + 255) / 256, 256>>>(wih, whh);               // 1
    k_deg<<<(N_EDGES + 255) / 256, 256>>>(ei);                        // 2
    k_scan1<<<SCAN_NB, 1024>>>();                                     // 3
    k_input<<<(N_NODES + 63) / 64, 256, smem_in>>>(x, w_in, b_in,     // 4 (profiled)
                                                   tw1, tb1, tw2, tb2);
    k_scan2<<<1, 64>>>();                                             // 5
    k_scan3<<<SCAN_NB, 1024>>>();                                     // 6 (+order)
    k_csr<<<(N_EDGES + 255) / 256, 256>>>(ei);                        // 7

    for (int it = 0; it < MAX_REC; it++) {
        k_agg<<<(N_NODES + 3) / 4, 256>>>(it);
        k_gru<<<(N_NODES + 63) / 64, 256, smem_gru>>>(bih, bhh, it);
    }
    k_out<<<(N_NODES + 31) / 32, 256>>>(wo, bo, out);
}

// round 11
// speedup vs baseline: 1.1907x; 1.0500x over previous
#include <cuda_runtime.h>
#include <math.h>

#define N_NODES 50000
#define N_EDGES 800000
#define IN_DIM  128
#define HID     96
#define OUT_DIM 64
#define MAX_REC 5
#define SCAN_NB ((N_NODES + 1023) / 1024)   // 49

typedef unsigned long long u64;

// ---------------- scratch (no allocations allowed) ----------------
__device__ float g_h[N_NODES * HID];
__device__ float g_agg[N_NODES * HID];
__device__ int   g_steps[N_NODES];
__device__ int   g_deg[N_NODES];
__device__ int   g_rowoff[N_NODES + 1];
__device__ int   g_cursor[N_NODES];
__device__ int   g_col[N_EDGES];
__device__ int   g_hist[8];
__device__ int   g_bcur[8];
__device__ int   g_order[N_NODES];
__device__ int   g_cnt[8];
__device__ int   g_bsum[64];
__device__ int   g_boff[64];
__device__ float g_wt_ih[3 * HID * HID];   // [chunk][k][j]
__device__ float g_wt_hh[3 * HID * HID];

// ---------------- f32x2 helpers ----------------
__device__ __forceinline__ u64 ffma2(u64 a, u64 b, u64 c) {
    u64 d;
    asm("fma.rn.f32x2 %0, %1, %2, %3;" : "=l"(d) : "l"(a), "l"(b), "l"(c));
    return d;
}
__device__ __forceinline__ u64 pack2(float x, float y) {
    u64 r;
    asm("mov.b64 %0, {%1, %2};" : "=l"(r) : "f"(x), "f"(y));
    return r;
}
__device__ __forceinline__ float2 unpack2(u64 v) {
    float2 r;
    asm("mov.b64 {%0, %1}, %2;" : "=f"(r.x), "=f"(r.y) : "l"(v));
    return r;
}
__device__ __forceinline__ float fast_sigmoid(float x) {
    return __fdividef(1.f, 1.f + __expf(-x));
}
__device__ __forceinline__ float fast_tanh(float x) {
    return 1.f - __fdividef(2.f, __expf(2.f * x) + 1.f);
}

// ---------------- fused init + weight transpose ----------------
__global__ void k_initwt(const float* __restrict__ wih, const float* __restrict__ whh) {
    int i = blockIdx.x * 256 + threadIdx.x;
    if (i < N_NODES) g_deg[i] = 0;
    if (i < 8) g_hist[i] = 0;
    if (i < 3 * HID * HID) {
        int chunk = i / (HID * HID);
        int r = i - chunk * HID * HID;
        int k = r / HID, j = r - k * HID;
        g_wt_ih[i] = wih[(chunk * HID + j) * HID + k];
        g_wt_hh[i] = whh[(chunk * HID + j) * HID + k];
    }
}

// ---------------- degree histogram ----------------
__global__ void k_deg(const int* __restrict__ ei) {
    int e = blockIdx.x * blockDim.x + threadIdx.x;
    if (e < N_EDGES) atomicAdd(&g_deg[ei[e]], 1);
}

// ---------------- multi-block scan ----------------
__global__ __launch_bounds__(1024) void k_scan1() {
    __shared__ int wsum[32];
    __shared__ int woff[32];
    int t = threadIdx.x, lane = t & 31, wid = t >> 5;
    int i = blockIdx.x * 1024 + t;
    int v = (i < N_NODES) ? g_deg[i] : 0;
    int s = v;
#pragma unroll
    for (int o = 1; o < 32; o <<= 1) {
        int u = __shfl_up_sync(0xffffffffu, s, o);
        if (lane >= o) s += u;
    }
    if (lane == 31) wsum[wid] = s;
    __syncthreads();
    if (wid == 0) {
        int ws = wsum[lane];
        int ss = ws;
#pragma unroll
        for (int o = 1; o < 32; o <<= 1) {
            int u = __shfl_up_sync(0xffffffffu, ss, o);
            if (lane >= o) ss += u;
        }
        woff[lane] = ss - ws;
        if (lane == 31) g_bsum[blockIdx.x] = ss;
    }
    __syncthreads();
    if (i < N_NODES) g_rowoff[i] = s - v + woff[wid];
}

// ---------------- fused input GEMM + relu + tau/steps ----------------
__global__ __launch_bounds__(256) void k_input(
    const float* __restrict__ x, const float* __restrict__ w_in,
    const float* __restrict__ b_in, const float* __restrict__ tw1,
    const float* __restrict__ tb1, const float* __restrict__ tw2,
    const float* __restrict__ tb2)
{
    extern __shared__ float sm_in[];
    float* xs_t = sm_in;               // [128][66]
    float* ts   = xs_t + 128 * 66;     // [128][16]
    int t = threadIdx.x;
    int node0 = blockIdx.x * 64;

#pragma unroll
    for (int idx = t; idx < 128 * 16; idx += 256) ts[idx] = tw1[idx];
#pragma unroll
    for (int idx = t; idx < 64 * 128; idx += 256) {
        int n = idx >> 7, k = idx & 127;
        int gn = node0 + n;
        xs_t[k * 66 + n] = (gn < N_NODES) ? x[gn * IN_DIM + k] : 0.f;
    }
    __syncthreads();

    int cj = t & 31;     // cols {cj, cj+32, cj+64}
    int pg = t >> 5;     // node pairs {pg, pg+8, pg+16, pg+24}

    u64 acc[3][4];
#pragma unroll
    for (int cc = 0; cc < 3; cc++) {
        float b = b_in[cj + 32 * cc];
        u64 bp = pack2(b, b);
#pragma unroll
        for (int q = 0; q < 4; q++) acc[cc][q] = bp;
    }
#pragma unroll 8
    for (int k = 0; k < 128; k++) {
        u64 wd[3];
#pragma unroll
        for (int cc = 0; cc < 3; cc++) {
            float w = __ldg(&w_in[k * 96 + cj + 32 * cc]);
            wd[cc] = pack2(w, w);
        }
        u64 ap[4];
#pragma unroll
        for (int q = 0; q < 4; q++)
            ap[q] = *(const u64*)&xs_t[k * 66 + 2 * (pg + 8 * q)];
#pragma unroll
        for (int cc = 0; cc < 3; cc++)
#pragma unroll
            for (int q = 0; q < 4; q++)
                acc[cc][q] = ffma2(wd[cc], ap[q], acc[cc][q]);
    }
#pragma unroll
    for (int cc = 0; cc < 3; cc++) {
        int col = cj + 32 * cc;
#pragma unroll
        for (int q = 0; q < 4; q++) {
            int n0 = node0 + 2 * (pg + 8 * q);
            float2 g = unpack2(acc[cc][q]);
            if (n0 < N_NODES)     g_h[n0 * HID + col]       = fmaxf(g.x, 0.f);
            if (n0 + 1 < N_NODES) g_h[(n0 + 1) * HID + col] = fmaxf(g.y, 0.f);
        }
    }

    // tau: 4 threads per node
    {
        int tn = t >> 2;
        int tj = t & 3;
        int gn = node0 + tn;
        float hh[4];
#pragma unroll
        for (int u = 0; u < 4; u++) hh[u] = tb1[tj + 4 * u];
#pragma unroll 4
        for (int k = 0; k < 128; k++) {
            float xv = xs_t[k * 66 + tn];
#pragma unroll
            for (int u = 0; u < 4; u++)
                hh[u] += xv * ts[k * 16 + tj + 4 * u];
        }
        float s = 0.f;
#pragma unroll
        for (int u = 0; u < 4; u++)
            s += fmaxf(hh[u], 0.f) * tw2[tj + 4 * u];
        s += __shfl_xor_sync(0xffffffffu, s, 1);
        s += __shfl_xor_sync(0xffffffffu, s, 2);
        if (tj == 0 && gn < N_NODES) {
            s += tb2[0];
            float sp = fmaxf(s, 0.f) + log1pf(expf(-fabsf(s)));
            float inv = 1.0f / sp;
            int st = (inv >= (float)MAX_REC) ? MAX_REC : (int)inv;
            g_steps[gn] = st;
            atomicAdd(&g_hist[st], 1);
        }
    }
}

__global__ void k_scan2() {
    __shared__ int sh[64];
    int t = threadIdx.x;
    sh[t] = (t < SCAN_NB) ? g_bsum[t] : 0;
    __syncthreads();
    if (t == 0) {
        int run = 0;
        for (int b = 0; b < SCAN_NB; b++) { g_boff[b] = run; run += sh[b]; }
        g_rowoff[N_NODES] = run;
        int suffix = 0;
        int start[6];
        for (int s = 5; s >= 0; s--) { start[s] = suffix; suffix += g_hist[s]; }
        for (int s = 0; s < 6; s++) g_bcur[s] = start[s];
        for (int it = 0; it < 5; it++) g_cnt[it] = start[it];
    }
}

// scan3 + order fused
__global__ __launch_bounds__(1024) void k_scan3() {
    int i = blockIdx.x * 1024 + threadIdx.x;
    if (i < N_NODES) {
        int v = g_rowoff[i] + g_boff[blockIdx.x];
        g_rowoff[i] = v;
        g_cursor[i] = v;
        int s = g_steps[i];
        int pos = atomicAdd(&g_bcur[s], 1);
        g_order[pos] = i;
    }
}

// ---------------- CSR fill ----------------
__global__ void k_csr(const int* __restrict__ ei) {
    int e = blockIdx.x * blockDim.x + threadIdx.x;
    if (e < N_EDGES) {
        int r = ei[e];
        int c = ei[N_EDGES + e];
        int pos = atomicAdd(&g_cursor[r], 1);
        g_col[pos] = c;
    }
}

// ---------------- edge aggregation: warp/node, deeper MLP (unroll 4) ---------
__global__ __launch_bounds__(256) void k_agg(int it) {
    int w = blockIdx.x * 8 + (threadIdx.x >> 5);
    if (w >= g_cnt[it]) return;
    int node = g_order[w];
    int lane = threadIdx.x & 31;
    int grp = lane >> 2;
    int l4  = lane & 3;
    int base = g_rowoff[node], end = g_rowoff[node + 1];

    const float4* hi4 = (const float4*)(g_h + node * HID);
    float4 hi[6], acc[6];
#pragma unroll
    for (int u = 0; u < 6; u++) {
        hi[u] = hi4[l4 + 4 * u];
        acc[u] = make_float4(0.f, 0.f, 0.f, 0.f);
    }

#pragma unroll 4
    for (int e = base + grp; e < end; e += 8) {
        int cc = __ldg(&g_col[e]);
        const float4* hp = (const float4*)(g_h + cc * HID);
#pragma unroll
        for (int u = 0; u < 6; u++) {
            float4 v = hp[l4 + 4 * u];
            acc[u].x += fabsf(v.x - hi[u].x);
            acc[u].y += fabsf(v.y - hi[u].y);
            acc[u].z += fabsf(v.z - hi[u].z);
            acc[u].w += fabsf(v.w - hi[u].w);
        }
    }
#pragma unroll
    for (int off = 4; off < 32; off <<= 1) {
#pragma unroll
        for (int u = 0; u < 6; u++) {
            acc[u].x += __shfl_xor_sync(0xffffffffu, acc[u].x, off);
            acc[u].y += __shfl_xor_sync(0xffffffffu, acc[u].y, off);
            acc[u].z += __shfl_xor_sync(0xffffffffu, acc[u].z, off);
            acc[u].w += __shfl_xor_sync(0xffffffffu, acc[u].w, off);
        }
    }
    if (grp == 0) {
        float4* ar = (float4*)(g_agg + (long long)node * HID);
#pragma unroll
        for (int u = 0; u < 6; u++) ar[l4 + 4 * u] = acc[u];
    }
}

// ---------------- GRU v3 (R7 exact): smem weights, f32x2, fast activations ---
__global__ __launch_bounds__(256, 1) void k_gru(
    const float* __restrict__ bih, const float* __restrict__ bhh, int it)
{
    extern __shared__ float sm_g[];
    float* agg_s = sm_g;                 // 6400
    float* h_s   = agg_s + 6400;         // 6400
    float* w0a   = h_s + 6400;           // 9216 (r: ih)
    float* w0b   = w0a + 9216;           // 9216 (r: hh)
    float* w1a   = w0b + 9216;           // 9216 (z: ih)
    float* w1b   = w1a + 9216;           // 9216 (z: hh)
    int* nodes_s = (int*)(w1b + 9216);

    int t = threadIdx.x;
    int cnt = g_cnt[it];
    int tile0 = blockIdx.x * 64;
    if (tile0 >= cnt) return;
    int nvalid = min(64, cnt - tile0);

    if (t < 64) nodes_s[t] = g_order[tile0 + min(t, nvalid - 1)];
    __syncthreads();
#pragma unroll
    for (int idx = t; idx < 64 * 24; idx += 256) {
        int n = idx / 24, c4 = idx - n * 24;
        int gn = nodes_s[n];
        ((float4*)(agg_s + n * 100))[c4] = ((const float4*)(g_agg + gn * HID))[c4];
        ((float4*)(h_s + n * 100))[c4]   = ((const float4*)(g_h + gn * HID))[c4];
    }
#pragma unroll
    for (int idx = t; idx < 2304; idx += 256) {
        ((float4*)w0a)[idx] = ((const float4*)g_wt_ih)[idx];
        ((float4*)w0b)[idx] = ((const float4*)g_wt_hh)[idx];
        ((float4*)w1a)[idx] = ((const float4*)(g_wt_ih + 9216))[idx];
        ((float4*)w1b)[idx] = ((const float4*)(g_wt_hh + 9216))[idx];
    }
    __syncthreads();

    int cp = t & 15;     // col-pairs {cp, cp+16, cp+32} (cols 2p, 2p+1)
    int ng = t >> 4;     // nodes 4ng..4ng+3
    int nb = 4 * ng;

    u64 accR[3][4], accZ[3][4];
#pragma unroll
    for (int cc = 0; cc < 3; cc++) {
        int c2 = 2 * (cp + 16 * cc);
        float2 bi0 = *(const float2*)&bih[c2];
        float2 bh0 = *(const float2*)&bhh[c2];
        float2 bi1 = *(const float2*)&bih[96 + c2];
        float2 bh1 = *(const float2*)&bhh[96 + c2];
        u64 bR = pack2(bi0.x + bh0.x, bi0.y + bh0.y);
        u64 bZ = pack2(bi1.x + bh1.x, bi1.y + bh1.y);
#pragma unroll
        for (int q = 0; q < 4; q++) { accR[cc][q] = bR; accZ[cc][q] = bZ; }
    }
#pragma unroll 4
    for (int k = 0; k < 96; k++) {
        u64 wra[3], wrb[3], wza[3], wzb[3];
#pragma unroll
        for (int cc = 0; cc < 3; cc++) {
            int o = k * 96 + 2 * (cp + 16 * cc);
            wra[cc] = *(const u64*)&w0a[o];
            wrb[cc] = *(const u64*)&w0b[o];
            wza[cc] = *(const u64*)&w1a[o];
            wzb[cc] = *(const u64*)&w1b[o];
        }
        u64 a2[4], h2[4];
#pragma unroll
        for (int q = 0; q < 4; q++) {
            float a  = agg_s[(nb + q) * 100 + k];
            float hv = h_s[(nb + q) * 100 + k];
            a2[q] = pack2(a, a);
            h2[q] = pack2(hv, hv);
        }
#pragma unroll
        for (int cc = 0; cc < 3; cc++)
#pragma unroll
            for (int q = 0; q < 4; q++) {
                accR[cc][q] = ffma2(wra[cc], a2[q], accR[cc][q]);
                accR[cc][q] = ffma2(wrb[cc], h2[q], accR[cc][q]);
                accZ[cc][q] = ffma2(wza[cc], a2[q], accZ[cc][q]);
                accZ[cc][q] = ffma2(wzb[cc], h2[q], accZ[cc][q]);
            }
    }
    u64 r_g[3][4], z_g[3][4];
#pragma unroll
    for (int cc = 0; cc < 3; cc++)
#pragma unroll
        for (int q = 0; q < 4; q++) {
            float2 gr = unpack2(accR[cc][q]);
            float2 gz = unpack2(accZ[cc][q]);
            r_g[cc][q] = pack2(fast_sigmoid(gr.x), fast_sigmoid(gr.y));
            z_g[cc][q] = pack2(fast_sigmoid(gz.x), fast_sigmoid(gz.y));
        }

    // chunk 2: candidate gate
    __syncthreads();
#pragma unroll
    for (int idx = t; idx < 2304; idx += 256) {
        ((float4*)w0a)[idx] = ((const float4*)(g_wt_ih + 18432))[idx];
        ((float4*)w0b)[idx] = ((const float4*)(g_wt_hh + 18432))[idx];
    }
    __syncthreads();

    u64 ai[3][4], ah[3][4];
#pragma unroll
    for (int cc = 0; cc < 3; cc++) {
        int c2 = 2 * (cp + 16 * cc);
        float2 b1 = *(const float2*)&bih[192 + c2];
        float2 b2 = *(const float2*)&bhh[192 + c2];
        u64 p1 = pack2(b1.x, b1.y), p2 = pack2(b2.x, b2.y);
#pragma unroll
        for (int q = 0; q < 4; q++) { ai[cc][q] = p1; ah[cc][q] = p2; }
    }
#pragma unroll 4
    for (int k = 0; k < 96; k++) {
        u64 wa[3], wb[3];
#pragma unroll
        for (int cc = 0; cc < 3; cc++) {
            int o = k * 96 + 2 * (cp + 16 * cc);
            wa[cc] = *(const u64*)&w0a[o];
            wb[cc] = *(const u64*)&w0b[o];
        }
        u64 a2[4], h2[4];
#pragma unroll
        for (int q = 0; q < 4; q++) {
            float a  = agg_s[(nb + q) * 100 + k];
            float hv = h_s[(nb + q) * 100 + k];
            a2[q] = pack2(a, a);
            h2[q] = pack2(hv, hv);
        }
#pragma unroll
        for (int cc = 0; cc < 3; cc++)
#pragma unroll
            for (int q = 0; q < 4; q++) {
                ai[cc][q] = ffma2(wa[cc], a2[q], ai[cc][q]);
                ah[cc][q] = ffma2(wb[cc], h2[q], ah[cc][q]);
            }
    }
#pragma unroll
    for (int cc = 0; cc < 3; cc++) {
        int c2 = 2 * (cp + 16 * cc);
#pragma unroll
        for (int q = 0; q < 4; q++) {
            int n = nb + q;
            float2 vi = unpack2(ai[cc][q]);
            float2 vh = unpack2(ah[cc][q]);
            float2 rr = unpack2(r_g[cc][q]);
            float2 zz = unpack2(z_g[cc][q]);
            float hold0 = h_s[n * 100 + c2];
            float hold1 = h_s[n * 100 + c2 + 1];
            float nv0 = fast_tanh(vi.x + rr.x * vh.x);
            float nv1 = fast_tanh(vi.y + rr.y * vh.y);
            float h0 = (1.f - zz.x) * nv0 + zz.x * hold0;
            float h1 = (1.f - zz.y) * nv1 + zz.y * hold1;
            *(float2*)&g_h[nodes_s[n] * HID + c2] = make_float2(h0, h1);
        }
    }
}

// ---------------- output GEMM ----------------
__global__ __launch_bounds__(256) void k_out(
    const float* __restrict__ wo, const float* __restrict__ bo,
    float* __restrict__ out)
{
    __shared__ float ws[96 * 64];
    __shared__ float hs[32 * 97];
    int t = threadIdx.x;
    int node0 = blockIdx.x * 32;
#pragma unroll
    for (int idx = t; idx < 96 * 64; idx += 256) ws[idx] = wo[idx];
#pragma unroll
    for (int idx = t; idx < 32 * 96; idx += 256) {
        int n = idx / 96, k = idx - n * 96;
        int gn = node0 + n;
        hs[n * 97 + k] = (gn < N_NODES) ? g_h[gn * HID + k] : 0.f;
    }
    __syncthreads();
    int j = t & 63, nt = t >> 6;
    float acc[8];
#pragma unroll
    for (int nn = 0; nn < 8; nn++) acc[nn] = bo[j];
#pragma unroll 4
    for (int k = 0; k < 96; k++) {
        float w = ws[k * 64 + j];
#pragma unroll
        for (int nn = 0; nn < 8; nn++)
            acc[nn] += hs[(nt + 4 * nn) * 97 + k] * w;
    }
#pragma unroll
    for (int nn = 0; nn < 8; nn++) {
        int gn = node0 + nt + 4 * nn;
        if (gn < N_NODES) out[gn * OUT_DIM + j] = acc[nn];
    }
}

// ---------------- launch ----------------
extern "C" void kernel_launch(void* const* d_in, const int* in_sizes, int n_in,
                              void* d_out, int out_size)
{
    const float* x    = (const float*)d_in[0];
    const int*   ei   = (const int*)d_in[1];
    const float* w_in = (const float*)d_in[2];
    const float* b_in = (const float*)d_in[3];
    const float* tw1  = (const float*)d_in[4];
    const float* tb1  = (const float*)d_in[5];
    const float* tw2  = (const float*)d_in[6];
    const float* tb2  = (const float*)d_in[7];
    const float* wih  = (const float*)d_in[8];
    const float* whh  = (const float*)d_in[9];
    const float* bih  = (const float*)d_in[10];
    const float* bhh  = (const float*)d_in[11];
    const float* wo   = (const float*)d_in[12];
    const float* bo   = (const float*)d_in[13];
    float* out = (float*)d_out;

    const int smem_in  = (128 * 66 + 128 * 16) * 4;                     // 41984 B
    const int smem_gru = (6400 * 2 + 9216 * 4) * 4 + 64 * 4;            // 198912 B
    cudaFuncSetAttribute(k_input, cudaFuncAttributeMaxDynamicSharedMemorySize, smem_in);
    cudaFuncSetAttribute(k_gru,   cudaFuncAttributeMaxDynamicSharedMemorySize, smem_gru);

    k_initwt<<<(N_NODES + 255) / 256, 256>>>(wih, whh);               // 1
    k_deg<<<(N_EDGES + 255) / 256, 256>>>(ei);                        // 2
    k_scan1<<<SCAN_NB, 1024>>>();                                     // 3
    k_input<<<(N_NODES + 63) / 64, 256, smem_in>>>(x, w_in, b_in,     // 4 (profiled)
                                                   tw1, tb1, tw2, tb2);
    k_scan2<<<1, 64>>>();                                             // 5
    k_scan3<<<SCAN_NB, 1024>>>();                                     // 6 (+order)
    k_csr<<<(N_EDGES + 255) / 256, 256>>>(ei);                        // 7

    for (int it = 0; it < MAX_REC; it++) {
        k_agg<<<(N_NODES + 7) / 8, 256>>>(it);
        k_gru<<<(N_NODES + 63) / 64, 256, smem_gru>>>(bih, bhh, it);
    }
    k_out<<<(N_NODES + 31) / 32, 256>>>(wo, bo, out);
}

// round 12
// speedup vs baseline: 1.2000x; 1.0078x over previous
#include <cuda_runtime.h>
#include <math.h>

#define N_NODES 50000
#define N_EDGES 800000
#define IN_DIM  128
#define HID     96
#define OUT_DIM 64
#define MAX_REC 5
#define SCAN_NB ((N_NODES + 1023) / 1024)   // 49

typedef unsigned long long u64;

// ---------------- scratch (no allocations allowed) ----------------
__device__ float g_h[N_NODES * HID];
__device__ float g_agg[N_NODES * HID];
__device__ int   g_steps[N_NODES];
__device__ int   g_deg[N_NODES];
__device__ int   g_rowoff[N_NODES + 1];
__device__ int   g_cursor[N_NODES];
__device__ int   g_col[N_EDGES];
__device__ int   g_hist[8];
__device__ int   g_bcur[8];
__device__ int   g_order[N_NODES];
__device__ int   g_cnt[8];
__device__ int   g_bsum[64];
__device__ int   g_boff[64];
__device__ float g_wt_ih[3 * HID * HID];   // [chunk][k][j]
__device__ float g_wt_hh[3 * HID * HID];

// ---------------- f32x2 helpers ----------------
__device__ __forceinline__ u64 ffma2(u64 a, u64 b, u64 c) {
    u64 d;
    asm("fma.rn.f32x2 %0, %1, %2, %3;" : "=l"(d) : "l"(a), "l"(b), "l"(c));
    return d;
}
__device__ __forceinline__ u64 pack2(float x, float y) {
    u64 r;
    asm("mov.b64 %0, {%1, %2};" : "=l"(r) : "f"(x), "f"(y));
    return r;
}
__device__ __forceinline__ float2 unpack2(u64 v) {
    float2 r;
    asm("mov.b64 {%0, %1}, %2;" : "=f"(r.x), "=f"(r.y) : "l"(v));
    return r;
}
__device__ __forceinline__ float fast_sigmoid(float x) {
    return __fdividef(1.f, 1.f + __expf(-x));
}
__device__ __forceinline__ float fast_tanh(float x) {
    return 1.f - __fdividef(2.f, __expf(2.f * x) + 1.f);
}

// ---------------- fused init + weight transpose ----------------
__global__ void k_initwt(const float* __restrict__ wih, const float* __restrict__ whh) {
    int i = blockIdx.x * 256 + threadIdx.x;
    if (i < N_NODES) g_deg[i] = 0;
    if (i < 8) g_hist[i] = 0;
    if (i < 3 * HID * HID) {
        int chunk = i / (HID * HID);
        int r = i - chunk * HID * HID;
        int k = r / HID, j = r - k * HID;
        g_wt_ih[i] = wih[(chunk * HID + j) * HID + k];
        g_wt_hh[i] = whh[(chunk * HID + j) * HID + k];
    }
}

// ---------------- degree histogram ----------------
__global__ void k_deg(const int* __restrict__ ei) {
    int e = blockIdx.x * blockDim.x + threadIdx.x;
    if (e < N_EDGES) atomicAdd(&g_deg[ei[e]], 1);
}

// ---------------- multi-block scan ----------------
__global__ __launch_bounds__(1024) void k_scan1() {
    __shared__ int wsum[32];
    __shared__ int woff[32];
    int t = threadIdx.x, lane = t & 31, wid = t >> 5;
    int i = blockIdx.x * 1024 + t;
    int v = (i < N_NODES) ? g_deg[i] : 0;
    int s = v;
#pragma unroll
    for (int o = 1; o < 32; o <<= 1) {
        int u = __shfl_up_sync(0xffffffffu, s, o);
        if (lane >= o) s += u;
    }
    if (lane == 31) wsum[wid] = s;
    __syncthreads();
    if (wid == 0) {
        int ws = wsum[lane];
        int ss = ws;
#pragma unroll
        for (int o = 1; o < 32; o <<= 1) {
            int u = __shfl_up_sync(0xffffffffu, ss, o);
            if (lane >= o) ss += u;
        }
        woff[lane] = ss - ws;
        if (lane == 31) g_bsum[blockIdx.x] = ss;
    }
    __syncthreads();
    if (i < N_NODES) g_rowoff[i] = s - v + woff[wid];
}

// ---------------- fused input GEMM + relu + tau/steps (R7 exact) ----------------
__global__ __launch_bounds__(256) void k_input(
    const float* __restrict__ x, const float* __restrict__ w_in,
    const float* __restrict__ b_in, const float* __restrict__ tw1,
    const float* __restrict__ tb1, const float* __restrict__ tw2,
    const float* __restrict__ tb2)
{
    extern __shared__ float sm_in[];
    float* xs_t = sm_in;               // [128][66]
    float* ts   = xs_t + 128 * 66;     // [128][16]
    int t = threadIdx.x;
    int node0 = blockIdx.x * 64;

#pragma unroll
    for (int idx = t; idx < 128 * 16; idx += 256) ts[idx] = tw1[idx];
#pragma unroll
    for (int idx = t; idx < 64 * 128; idx += 256) {
        int n = idx >> 7, k = idx & 127;
        int gn = node0 + n;
        xs_t[k * 66 + n] = (gn < N_NODES) ? x[gn * IN_DIM + k] : 0.f;
    }
    __syncthreads();

    int cj = t & 31;     // cols {cj, cj+32, cj+64}
    int pg = t >> 5;     // node pairs {pg, pg+8, pg+16, pg+24}

    u64 acc[3][4];
#pragma unroll
    for (int cc = 0; cc < 3; cc++) {
        float b = b_in[cj + 32 * cc];
        u64 bp = pack2(b, b);
#pragma unroll
        for (int q = 0; q < 4; q++) acc[cc][q] = bp;
    }
#pragma unroll 8
    for (int k = 0; k < 128; k++) {
        u64 wd[3];
#pragma unroll
        for (int cc = 0; cc < 3; cc++) {
            float w = __ldg(&w_in[k * 96 + cj + 32 * cc]);
            wd[cc] = pack2(w, w);
        }
        u64 ap[4];
#pragma unroll
        for (int q = 0; q < 4; q++)
            ap[q] = *(const u64*)&xs_t[k * 66 + 2 * (pg + 8 * q)];
#pragma unroll
        for (int cc = 0; cc < 3; cc++)
#pragma unroll
            for (int q = 0; q < 4; q++)
                acc[cc][q] = ffma2(wd[cc], ap[q], acc[cc][q]);
    }
#pragma unroll
    for (int cc = 0; cc < 3; cc++) {
        int col = cj + 32 * cc;
#pragma unroll
        for (int q = 0; q < 4; q++) {
            int n0 = node0 + 2 * (pg + 8 * q);
            float2 g = unpack2(acc[cc][q]);
            if (n0 < N_NODES)     g_h[n0 * HID + col]       = fmaxf(g.x, 0.f);
            if (n0 + 1 < N_NODES) g_h[(n0 + 1) * HID + col] = fmaxf(g.y, 0.f);
        }
    }

    // tau: 4 threads per node
    {
        int tn = t >> 2;
        int tj = t & 3;
        int gn = node0 + tn;
        float hh[4];
#pragma unroll
        for (int u = 0; u < 4; u++) hh[u] = tb1[tj + 4 * u];
#pragma unroll 4
        for (int k = 0; k < 128; k++) {
            float xv = xs_t[k * 66 + tn];
#pragma unroll
            for (int u = 0; u < 4; u++)
                hh[u] += xv * ts[k * 16 + tj + 4 * u];
        }
        float s = 0.f;
#pragma unroll
        for (int u = 0; u < 4; u++)
            s += fmaxf(hh[u], 0.f) * tw2[tj + 4 * u];
        s += __shfl_xor_sync(0xffffffffu, s, 1);
        s += __shfl_xor_sync(0xffffffffu, s, 2);
        if (tj == 0 && gn < N_NODES) {
            s += tb2[0];
            float sp = fmaxf(s, 0.f) + log1pf(expf(-fabsf(s)));
            float inv = 1.0f / sp;
            int st = (inv >= (float)MAX_REC) ? MAX_REC : (int)inv;
            g_steps[gn] = st;
            atomicAdd(&g_hist[st], 1);
        }
    }
}

__global__ void k_scan2() {
    __shared__ int sh[64];
    int t = threadIdx.x;
    sh[t] = (t < SCAN_NB) ? g_bsum[t] : 0;
    __syncthreads();
    if (t == 0) {
        int run = 0;
        for (int b = 0; b < SCAN_NB; b++) { g_boff[b] = run; run += sh[b]; }
        g_rowoff[N_NODES] = run;
        int suffix = 0;
        int start[6];
        for (int s = 5; s >= 0; s--) { start[s] = suffix; suffix += g_hist[s]; }
        for (int s = 0; s < 6; s++) g_bcur[s] = start[s];
        for (int it = 0; it < 5; it++) g_cnt[it] = start[it];
    }
}

// scan3 + order fused
__global__ __launch_bounds__(1024) void k_scan3() {
    int i = blockIdx.x * 1024 + threadIdx.x;
    if (i < N_NODES) {
        int v = g_rowoff[i] + g_boff[blockIdx.x];
        g_rowoff[i] = v;
        g_cursor[i] = v;
        int s = g_steps[i];
        int pos = atomicAdd(&g_bcur[s], 1);
        g_order[pos] = i;
    }
}

// ---------------- CSR fill ----------------
__global__ void k_csr(const int* __restrict__ ei) {
    int e = blockIdx.x * blockDim.x + threadIdx.x;
    if (e < N_EDGES) {
        int r = ei[e];
        int c = ei[N_EDGES + e];
        int pos = atomicAdd(&g_cursor[r], 1);
        g_col[pos] = c;
    }
}

// ---------------- edge aggregation (R7 exact + PDL) ----------------
// preamble (index reads; safe: gru never writes CSR/order) -> dep-sync -> trigger
__global__ __launch_bounds__(256) void k_agg(int it) {
    int w = blockIdx.x * 8 + (threadIdx.x >> 5);
    if (w >= g_cnt[it]) {                 // g_cnt: written far upstream, safe pre-sync
        cudaGridDependencySynchronize();  // keep semantics simple for exiting warps
        return;
    }
    int node = g_order[w];
    int lane = threadIdx.x & 31;
    int grp = lane >> 2;
    int l4  = lane & 3;
    int base = g_rowoff[node], end = g_rowoff[node + 1];

    cudaGridDependencySynchronize();      // wait for gru(it-1): g_h now final
    cudaTriggerProgrammaticLaunchCompletion();  // past sync -> successor may pre-stage

    const float4* hi4 = (const float4*)(g_h + node * HID);
    float4 hi[6], acc[6];
#pragma unroll
    for (int u = 0; u < 6; u++) {
        hi[u] = hi4[l4 + 4 * u];
        acc[u] = make_float4(0.f, 0.f, 0.f, 0.f);
    }

#pragma unroll 2
    for (int e = base + grp; e < end; e += 8) {
        int cc = __ldg(&g_col[e]);
        const float4* hp = (const float4*)(g_h + cc * HID);
#pragma unroll
        for (int u = 0; u < 6; u++) {
            float4 v = hp[l4 + 4 * u];
            acc[u].x += fabsf(v.x - hi[u].x);
            acc[u].y += fabsf(v.y - hi[u].y);
            acc[u].z += fabsf(v.z - hi[u].z);
            acc[u].w += fabsf(v.w - hi[u].w);
        }
    }
#pragma unroll
    for (int off = 4; off < 32; off <<= 1) {
#pragma unroll
        for (int u = 0; u < 6; u++) {
            acc[u].x += __shfl_xor_sync(0xffffffffu, acc[u].x, off);
            acc[u].y += __shfl_xor_sync(0xffffffffu, acc[u].y, off);
            acc[u].z += __shfl_xor_sync(0xffffffffu, acc[u].z, off);
            acc[u].w += __shfl_xor_sync(0xffffffffu, acc[u].w, off);
        }
    }
    if (grp == 0) {
        float4* ar = (float4*)(g_agg + (long long)node * HID);
#pragma unroll
        for (int u = 0; u < 6; u++) ar[l4 + 4 * u] = acc[u];
    }
}

// ---------------- GRU (R7 math + PDL) ----------------
// preamble: nodes + h_s + ALL r/z weight staging (none written by agg) overlap
// the tail of agg(it); dep-sync; trigger; then agg_s staging + compute.
__global__ __launch_bounds__(256, 1) void k_gru(
    const float* __restrict__ bih, const float* __restrict__ bhh, int it)
{
    extern __shared__ float sm_g[];
    float* agg_s = sm_g;                 // 6400
    float* h_s   = agg_s + 6400;         // 6400
    float* w0a   = h_s + 6400;           // 9216 (r: ih)
    float* w0b   = w0a + 9216;           // 9216 (r: hh)
    float* w1a   = w0b + 9216;           // 9216 (z: ih)
    float* w1b   = w1a + 9216;           // 9216 (z: hh)
    int* nodes_s = (int*)(w1b + 9216);

    int t = threadIdx.x;
    int cnt = g_cnt[it];
    int tile0 = blockIdx.x * 64;
    if (tile0 >= cnt) {
        cudaGridDependencySynchronize();
        return;
    }
    int nvalid = min(64, cnt - tile0);

    if (t < 64) nodes_s[t] = g_order[tile0 + min(t, nvalid - 1)];
    __syncthreads();
    // ---- preamble staging (independent of agg(it)) ----
#pragma unroll
    for (int idx = t; idx < 64 * 24; idx += 256) {
        int n = idx / 24, c4 = idx - n * 24;
        int gn = nodes_s[n];
        ((float4*)(h_s + n * 100))[c4] = ((const float4*)(g_h + gn * HID))[c4];
    }
#pragma unroll
    for (int idx = t; idx < 2304; idx += 256) {
        ((float4*)w0a)[idx] = ((const float4*)g_wt_ih)[idx];
        ((float4*)w0b)[idx] = ((const float4*)g_wt_hh)[idx];
        ((float4*)w1a)[idx] = ((const float4*)(g_wt_ih + 9216))[idx];
        ((float4*)w1b)[idx] = ((const float4*)(g_wt_hh + 9216))[idx];
    }

    cudaGridDependencySynchronize();     // agg(it) done: g_agg valid
    cudaTriggerProgrammaticLaunchCompletion();

#pragma unroll
    for (int idx = t; idx < 64 * 24; idx += 256) {
        int n = idx / 24, c4 = idx - n * 24;
        int gn = nodes_s[n];
        ((float4*)(agg_s + n * 100))[c4] = ((const float4*)(g_agg + gn * HID))[c4];
    }
    __syncthreads();

    int cp = t & 15;     // col-pairs {cp, cp+16, cp+32} (cols 2p, 2p+1)
    int ng = t >> 4;     // nodes 4ng..4ng+3
    int nb = 4 * ng;

    u64 accR[3][4], accZ[3][4];
#pragma unroll
    for (int cc = 0; cc < 3; cc++) {
        int c2 = 2 * (cp + 16 * cc);
        float2 bi0 = *(const float2*)&bih[c2];
        float2 bh0 = *(const float2*)&bhh[c2];
        float2 bi1 = *(const float2*)&bih[96 + c2];
        float2 bh1 = *(const float2*)&bhh[96 + c2];
        u64 bR = pack2(bi0.x + bh0.x, bi0.y + bh0.y);
        u64 bZ = pack2(bi1.x + bh1.x, bi1.y + bh1.y);
#pragma unroll
        for (int q = 0; q < 4; q++) { accR[cc][q] = bR; accZ[cc][q] = bZ; }
    }
#pragma unroll 4
    for (int k = 0; k < 96; k++) {
        u64 wra[3], wrb[3], wza[3], wzb[3];
#pragma unroll
        for (int cc = 0; cc < 3; cc++) {
            int o = k * 96 + 2 * (cp + 16 * cc);
            wra[cc] = *(const u64*)&w0a[o];
            wrb[cc] = *(const u64*)&w0b[o];
            wza[cc] = *(const u64*)&w1a[o];
            wzb[cc] = *(const u64*)&w1b[o];
        }
        u64 a2[4], h2[4];
#pragma unroll
        for (int q = 0; q < 4; q++) {
            float a  = agg_s[(nb + q) * 100 + k];
            float hv = h_s[(nb + q) * 100 + k];
            a2[q] = pack2(a, a);
            h2[q] = pack2(hv, hv);
        }
#pragma unroll
        for (int cc = 0; cc < 3; cc++)
#pragma unroll
            for (int q = 0; q < 4; q++) {
                accR[cc][q] = ffma2(wra[cc], a2[q], accR[cc][q]);
                accR[cc][q] = ffma2(wrb[cc], h2[q], accR[cc][q]);
                accZ[cc][q] = ffma2(wza[cc], a2[q], accZ[cc][q]);
                accZ[cc][q] = ffma2(wzb[cc], h2[q], accZ[cc][q]);
            }
    }
    u64 r_g[3][4], z_g[3][4];
#pragma unroll
    for (int cc = 0; cc < 3; cc++)
#pragma unroll
        for (int q = 0; q < 4; q++) {
            float2 gr = unpack2(accR[cc][q]);
            float2 gz = unpack2(accZ[cc][q]);
            r_g[cc][q] = pack2(fast_sigmoid(gr.x), fast_sigmoid(gr.y));
            z_g[cc][q] = pack2(fast_sigmoid(gz.x), fast_sigmoid(gz.y));
        }

    // chunk 2: candidate gate
    __syncthreads();
#pragma unroll
    for (int idx = t; idx < 2304; idx += 256) {
        ((float4*)w0a)[idx] = ((const float4*)(g_wt_ih + 18432))[idx];
        ((float4*)w0b)[idx] = ((const float4*)(g_wt_hh + 18432))[idx];
    }
    __syncthreads();

    u64 ai[3][4], ah[3][4];
#pragma unroll
    for (int cc = 0; cc < 3; cc++) {
        int c2 = 2 * (cp + 16 * cc);
        float2 b1 = *(const float2*)&bih[192 + c2];
        float2 b2 = *(const float2*)&bhh[192 + c2];
        u64 p1 = pack2(b1.x, b1.y), p2 = pack2(b2.x, b2.y);
#pragma unroll
        for (int q = 0; q < 4; q++) { ai[cc][q] = p1; ah[cc][q] = p2; }
    }
#pragma unroll 4
    for (int k = 0; k < 96; k++) {
        u64 wa[3], wb[3];
#pragma unroll
        for (int cc = 0; cc < 3; cc++) {
            int o = k * 96 + 2 * (cp + 16 * cc);
            wa[cc] = *(const u64*)&w0a[o];
            wb[cc] = *(const u64*)&w0b[o];
        }
        u64 a2[4], h2[4];
#pragma unroll
        for (int q = 0; q < 4; q++) {
            float a  = agg_s[(nb + q) * 100 + k];
            float hv = h_s[(nb + q) * 100 + k];
            a2[q] = pack2(a, a);
            h2[q] = pack2(hv, hv);
        }
#pragma unroll
        for (int cc = 0; cc < 3; cc++)
#pragma unroll
            for (int q = 0; q < 4; q++) {
                ai[cc][q] = ffma2(wa[cc], a2[q], ai[cc][q]);
                ah[cc][q] = ffma2(wb[cc], h2[q], ah[cc][q]);
            }
    }
#pragma unroll
    for (int cc = 0; cc < 3; cc++) {
        int c2 = 2 * (cp + 16 * cc);
#pragma unroll
        for (int q = 0; q < 4; q++) {
            int n = nb + q;
            float2 vi = unpack2(ai[cc][q]);
            float2 vh = unpack2(ah[cc][q]);
            float2 rr = unpack2(r_g[cc][q]);
            float2 zz = unpack2(z_g[cc][q]);
            float hold0 = h_s[n * 100 + c2];
            float hold1 = h_s[n * 100 + c2 + 1];
            float nv0 = fast_tanh(vi.x + rr.x * vh.x);
            float nv1 = fast_tanh(vi.y + rr.y * vh.y);
            float h0 = (1.f - zz.x) * nv0 + zz.x * hold0;
            float h1 = (1.f - zz.y) * nv1 + zz.y * hold1;
            *(float2*)&g_h[nodes_s[n] * HID + c2] = make_float2(h0, h1);
        }
    }
}

// ---------------- output GEMM (+PDL: w_out staged pre-sync) ----------------
__global__ __launch_bounds__(256) void k_out(
    const float* __restrict__ wo, const float* __restrict__ bo,
    float* __restrict__ out)
{
    __shared__ float ws[96 * 64];
    __shared__ float hs[32 * 97];
    int t = threadIdx.x;
    int node0 = blockIdx.x * 32;
#pragma unroll
    for (int idx = t; idx < 96 * 64; idx += 256) ws[idx] = wo[idx];

    cudaGridDependencySynchronize();     // gru(4) done: g_h final

#pragma unroll
    for (int idx = t; idx < 32 * 96; idx += 256) {
        int n = idx / 96, k = idx - n * 96;
        int gn = node0 + n;
        hs[n * 97 + k] = (gn < N_NODES) ? g_h[gn * HID + k] : 0.f;
    }
    __syncthreads();
    int j = t & 63, nt = t >> 6;
    float acc[8];
#pragma unroll
    for (int nn = 0; nn < 8; nn++) acc[nn] = bo[j];
#pragma unroll 4
    for (int k = 0; k < 96; k++) {
        float w = ws[k * 64 + j];
#pragma unroll
        for (int nn = 0; nn < 8; nn++)
            acc[nn] += hs[(nt + 4 * nn) * 97 + k] * w;
    }
#pragma unroll
    for (int nn = 0; nn < 8; nn++) {
        int gn = node0 + nt + 4 * nn;
        if (gn < N_NODES) out[gn * OUT_DIM + j] = acc[nn];
    }
}

// ---------------- launch ----------------
extern "C" void kernel_launch(void* const* d_in, const int* in_sizes, int n_in,
                              void* d_out, int out_size)
{
    const float* x    = (const float*)d_in[0];
    const int*   ei   = (const int*)d_in[1];
    const float* w_in = (const float*)d_in[2];
    const float* b_in = (const float*)d_in[3];
    const float* tw1  = (const float*)d_in[4];
    const float* tb1  = (const float*)d_in[5];
    const float* tw2  = (const float*)d_in[6];
    const float* tb2  = (const float*)d_in[7];
    const float* wih  = (const float*)d_in[8];
    const float* whh  = (const float*)d_in[9];
    const float* bih  = (const float*)d_in[10];
    const float* bhh  = (const float*)d_in[11];
    const float* wo   = (const float*)d_in[12];
    const float* bo   = (const float*)d_in[13];
    float* out = (float*)d_out;

    const int smem_in  = (128 * 66 + 128 * 16) * 4;                     // 41984 B
    const int smem_gru = (6400 * 2 + 9216 * 4) * 4 + 64 * 4;            // 198912 B
    cudaFuncSetAttribute(k_input, cudaFuncAttributeMaxDynamicSharedMemorySize, smem_in);
    cudaFuncSetAttribute(k_gru,   cudaFuncAttributeMaxDynamicSharedMemorySize, smem_gru);

    k_initwt<<<(N_NODES + 255) / 256, 256>>>(wih, whh);               // 1
    k_deg<<<(N_EDGES + 255) / 256, 256>>>(ei);                        // 2
    k_scan1<<<SCAN_NB, 1024>>>();                                     // 3
    k_input<<<(N_NODES + 63) / 64, 256, smem_in>>>(x, w_in, b_in,     // 4 (profiled)
                                                   tw1, tb1, tw2, tb2);
    k_scan2<<<1, 64>>>();                                             // 5
    k_scan3<<<SCAN_NB, 1024>>>();                                     // 6 (+order)
    k_csr<<<(N_EDGES + 255) / 256, 256>>>(ei);                        // 7

    // PDL-attributed loop launches
    cudaLaunchAttribute pdl_attr[1];
    pdl_attr[0].id = cudaLaunchAttributeProgrammaticStreamSerialization;
    pdl_attr[0].val.programmaticStreamSerializationAllowed = 1;

    for (int it = 0; it < MAX_REC; it++) {
        {
            cudaLaunchConfig_t cfg = {};
            cfg.gridDim = dim3((N_NODES + 7) / 8, 1, 1);
            cfg.blockDim = dim3(256, 1, 1);
            cfg.dynamicSmemBytes = 0;
            cfg.attrs = pdl_attr;
            cfg.numAttrs = 1;
            cudaLaunchKernelEx(&cfg, k_agg, it);
        }
        {
            cudaLaunchConfig_t cfg = {};
            cfg.gridDim = dim3((N_NODES + 63) / 64, 1, 1);
            cfg.blockDim = dim3(256, 1, 1);
            cfg.dynamicSmemBytes = smem_gru;
            cfg.attrs = pdl_attr;
            cfg.numAttrs = 1;
            cudaLaunchKernelEx(&cfg, k_gru, bih, bhh, it);
        }
    }
    {
        cudaLaunchConfig_t cfg = {};
        cfg.gridDim = dim3((N_NODES + 31) / 32, 1, 1);
        cfg.blockDim = dim3(256, 1, 1);
        cfg.dynamicSmemBytes = 0;
        cfg.attrs = pdl_attr;
        cfg.numAttrs = 1;
        cudaLaunchKernelEx(&cfg, k_out, wo, bo, out);
    }
}

// round 13
// speedup vs baseline: 1.2058x; 1.0048x over previous
#include <cuda_runtime.h>
#include <math.h>

#define N_NODES 50000
#define N_EDGES 800000
#define IN_DIM  128
#define HID     96
#define OUT_DIM 64
#define MAX_REC 5
#define SCAN_NB ((N_NODES + 1023) / 1024)   // 49

typedef unsigned long long u64;

// ---------------- scratch (no allocations allowed) ----------------
__device__ float g_h[N_NODES * HID];
__device__ float g_agg[N_NODES * HID];
__device__ int   g_steps[N_NODES];
__device__ int   g_deg[N_NODES];
__device__ int   g_rowoff[N_NODES + 1];
__device__ int   g_cursor[N_NODES];
__device__ int   g_col[N_EDGES];
__device__ int   g_hist[8];
__device__ int   g_bcur[8];
__device__ int   g_order[N_NODES];
__device__ int   g_cnt[8];
__device__ int   g_bsum[64];
__device__ int   g_boff[64];
__device__ float g_wt_ih[3 * HID * HID];   // [chunk][k][j]
__device__ float g_wt_hh[3 * HID * HID];

// ---------------- f32x2 helpers ----------------
__device__ __forceinline__ u64 ffma2(u64 a, u64 b, u64 c) {
    u64 d;
    asm("fma.rn.f32x2 %0, %1, %2, %3;" : "=l"(d) : "l"(a), "l"(b), "l"(c));
    return d;
}
__device__ __forceinline__ u64 pack2(float x, float y) {
    u64 r;
    asm("mov.b64 %0, {%1, %2};" : "=l"(r) : "f"(x), "f"(y));
    return r;
}
__device__ __forceinline__ float2 unpack2(u64 v) {
    float2 r;
    asm("mov.b64 {%0, %1}, %2;" : "=f"(r.x), "=f"(r.y) : "l"(v));
    return r;
}
__device__ __forceinline__ float fast_sigmoid(float x) {
    return __fdividef(1.f, 1.f + __expf(-x));
}
__device__ __forceinline__ float fast_tanh(float x) {
    return 1.f - __fdividef(2.f, __expf(2.f * x) + 1.f);
}

// ---------------- fused init + weight transpose ----------------
__global__ void k_initwt(const float* __restrict__ wih, const float* __restrict__ whh) {
    int i = blockIdx.x * 256 + threadIdx.x;
    if (i < N_NODES) g_deg[i] = 0;
    if (i < 8) g_hist[i] = 0;
    if (i < 3 * HID * HID) {
        int chunk = i / (HID * HID);
        int r = i - chunk * HID * HID;
        int k = r / HID, j = r - k * HID;
        g_wt_ih[i] = wih[(chunk * HID + j) * HID + k];
        g_wt_hh[i] = whh[(chunk * HID + j) * HID + k];
    }
}

// ---------------- degree histogram ----------------
__global__ void k_deg(const int* __restrict__ ei) {
    int e = blockIdx.x * blockDim.x + threadIdx.x;
    if (e < N_EDGES) atomicAdd(&g_deg[ei[e]], 1);
}

// ---------------- multi-block scan ----------------
__global__ __launch_bounds__(1024) void k_scan1() {
    __shared__ int wsum[32];
    __shared__ int woff[32];
    int t = threadIdx.x, lane = t & 31, wid = t >> 5;
    int i = blockIdx.x * 1024 + t;
    int v = (i < N_NODES) ? g_deg[i] : 0;
    int s = v;
#pragma unroll
    for (int o = 1; o < 32; o <<= 1) {
        int u = __shfl_up_sync(0xffffffffu, s, o);
        if (lane >= o) s += u;
    }
    if (lane == 31) wsum[wid] = s;
    __syncthreads();
    if (wid == 0) {
        int ws = wsum[lane];
        int ss = ws;
#pragma unroll
        for (int o = 1; o < 32; o <<= 1) {
            int u = __shfl_up_sync(0xffffffffu, ss, o);
            if (lane >= o) ss += u;
        }
        woff[lane] = ss - ws;
        if (lane == 31) g_bsum[blockIdx.x] = ss;
    }
    __syncthreads();
    if (i < N_NODES) g_rowoff[i] = s - v + woff[wid];
}

// ---------------- fused input GEMM + relu + tau/steps ----------------
// tau weights staged permuted so each thread's 4 cols are one float4.
__global__ __launch_bounds__(256) void k_input(
    const float* __restrict__ x, const float* __restrict__ w_in,
    const float* __restrict__ b_in, const float* __restrict__ tw1,
    const float* __restrict__ tb1, const float* __restrict__ tw2,
    const float* __restrict__ tb2)
{
    extern __shared__ float sm_in[];
    float* xs_t = sm_in;               // [128][66]
    float* ts   = xs_t + 128 * 66;     // [128][16], permuted: ts[k][tj*4+u] = tw1[k][tj+4u]
    int t = threadIdx.x;
    int node0 = blockIdx.x * 64;

#pragma unroll
    for (int idx = t; idx < 128 * 16; idx += 256) {
        int k = idx >> 4, p = idx & 15;
        ts[idx] = tw1[k * 16 + ((p >> 2) + 4 * (p & 3))];
    }
#pragma unroll
    for (int idx = t; idx < 64 * 128; idx += 256) {
        int n = idx >> 7, k = idx & 127;
        int gn = node0 + n;
        xs_t[k * 66 + n] = (gn < N_NODES) ? x[gn * IN_DIM + k] : 0.f;
    }
    __syncthreads();

    int cj = t & 31;     // cols {cj, cj+32, cj+64}
    int pg = t >> 5;     // node pairs {pg, pg+8, pg+16, pg+24}

    u64 acc[3][4];
#pragma unroll
    for (int cc = 0; cc < 3; cc++) {
        float b = b_in[cj + 32 * cc];
        u64 bp = pack2(b, b);
#pragma unroll
        for (int q = 0; q < 4; q++) acc[cc][q] = bp;
    }
#pragma unroll 8
    for (int k = 0; k < 128; k++) {
        u64 wd[3];
#pragma unroll
        for (int cc = 0; cc < 3; cc++) {
            float w = __ldg(&w_in[k * 96 + cj + 32 * cc]);
            wd[cc] = pack2(w, w);
        }
        u64 ap[4];
#pragma unroll
        for (int q = 0; q < 4; q++)
            ap[q] = *(const u64*)&xs_t[k * 66 + 2 * (pg + 8 * q)];
#pragma unroll
        for (int cc = 0; cc < 3; cc++)
#pragma unroll
            for (int q = 0; q < 4; q++)
                acc[cc][q] = ffma2(wd[cc], ap[q], acc[cc][q]);
    }
#pragma unroll
    for (int cc = 0; cc < 3; cc++) {
        int col = cj + 32 * cc;
#pragma unroll
        for (int q = 0; q < 4; q++) {
            int n0 = node0 + 2 * (pg + 8 * q);
            float2 g = unpack2(acc[cc][q]);
            if (n0 < N_NODES)     g_h[n0 * HID + col]       = fmaxf(g.x, 0.f);
            if (n0 + 1 < N_NODES) g_h[(n0 + 1) * HID + col] = fmaxf(g.y, 0.f);
        }
    }

    // tau: 4 threads per node, weight quad = one LDS.128
    {
        int tn = t >> 2;
        int tj = t & 3;
        int gn = node0 + tn;
        float hh[4];
#pragma unroll
        for (int u = 0; u < 4; u++) hh[u] = tb1[tj + 4 * u];
#pragma unroll 4
        for (int k = 0; k < 128; k++) {
            float xv = xs_t[k * 66 + tn];
            float4 wv = *(const float4*)&ts[k * 16 + tj * 4];
            hh[0] += xv * wv.x;
            hh[1] += xv * wv.y;
            hh[2] += xv * wv.z;
            hh[3] += xv * wv.w;
        }
        float s = 0.f;
#pragma unroll
        for (int u = 0; u < 4; u++)
            s += fmaxf(hh[u], 0.f) * tw2[tj + 4 * u];
        s += __shfl_xor_sync(0xffffffffu, s, 1);
        s += __shfl_xor_sync(0xffffffffu, s, 2);
        if (tj == 0 && gn < N_NODES) {
            s += tb2[0];
            float sp = fmaxf(s, 0.f) + log1pf(expf(-fabsf(s)));
            float inv = 1.0f / sp;
            int st = (inv >= (float)MAX_REC) ? MAX_REC : (int)inv;
            g_steps[gn] = st;
            atomicAdd(&g_hist[st], 1);
        }
    }
}

__global__ void k_scan2() {
    __shared__ int sh[64];
    int t = threadIdx.x;
    sh[t] = (t < SCAN_NB) ? g_bsum[t] : 0;
    __syncthreads();
    if (t == 0) {
        int run = 0;
        for (int b = 0; b < SCAN_NB; b++) { g_boff[b] = run; run += sh[b]; }
        g_rowoff[N_NODES] = run;
        int suffix = 0;
        int start[6];
        for (int s = 5; s >= 0; s--) { start[s] = suffix; suffix += g_hist[s]; }
        for (int s = 0; s < 6; s++) g_bcur[s] = start[s];
        for (int it = 0; it < 5; it++) g_cnt[it] = start[it];
    }
}

// scan3 + order fused
__global__ __launch_bounds__(1024) void k_scan3() {
    int i = blockIdx.x * 1024 + threadIdx.x;
    if (i < N_NODES) {
        int v = g_rowoff[i] + g_boff[blockIdx.x];
        g_rowoff[i] = v;
        g_cursor[i] = v;
        int s = g_steps[i];
        int pos = atomicAdd(&g_bcur[s], 1);
        g_order[pos] = i;
    }
}

// ---------------- CSR fill ----------------
__global__ void k_csr(const int* __restrict__ ei) {
    int e = blockIdx.x * blockDim.x + threadIdx.x;
    if (e < N_EDGES) {
        int r = ei[e];
        int c = ei[N_EDGES + e];
        int pos = atomicAdd(&g_cursor[r], 1);
        g_col[pos] = c;
    }
}

// ---------------- edge aggregation (R7 exact) ----------------
__global__ __launch_bounds__(256) void k_agg(int it) {
    int w = blockIdx.x * 8 + (threadIdx.x >> 5);
    if (w >= g_cnt[it]) return;
    int node = g_order[w];
    int lane = threadIdx.x & 31;
    int grp = lane >> 2;
    int l4  = lane & 3;
    int base = g_rowoff[node], end = g_rowoff[node + 1];

    const float4* hi4 = (const float4*)(g_h + node * HID);
    float4 hi[6], acc[6];
#pragma unroll
    for (int u = 0; u < 6; u++) {
        hi[u] = hi4[l4 + 4 * u];
        acc[u] = make_float4(0.f, 0.f, 0.f, 0.f);
    }

#pragma unroll 2
    for (int e = base + grp; e < end; e += 8) {
        int cc = __ldg(&g_col[e]);
        const float4* hp = (const float4*)(g_h + cc * HID);
#pragma unroll
        for (int u = 0; u < 6; u++) {
            float4 v = hp[l4 + 4 * u];
            acc[u].x += fabsf(v.x - hi[u].x);
            acc[u].y += fabsf(v.y - hi[u].y);
            acc[u].z += fabsf(v.z - hi[u].z);
            acc[u].w += fabsf(v.w - hi[u].w);
        }
    }
#pragma unroll
    for (int off = 4; off < 32; off <<= 1) {
#pragma unroll
        for (int u = 0; u < 6; u++) {
            acc[u].x += __shfl_xor_sync(0xffffffffu, acc[u].x, off);
            acc[u].y += __shfl_xor_sync(0xffffffffu, acc[u].y, off);
            acc[u].z += __shfl_xor_sync(0xffffffffu, acc[u].z, off);
            acc[u].w += __shfl_xor_sync(0xffffffffu, acc[u].w, off);
        }
    }
    if (grp == 0) {
        float4* ar = (float4*)(g_agg + (long long)node * HID);
#pragma unroll
        for (int u = 0; u < 6; u++) ar[l4 + 4 * u] = acc[u];
    }
}

// ---------------- GRU v3 (R7 exact) ----------------
__global__ __launch_bounds__(256, 1) void k_gru(
    const float* __restrict__ bih, const float* __restrict__ bhh, int it)
{
    extern __shared__ float sm_g[];
    float* agg_s = sm_g;                 // 6400
    float* h_s   = agg_s + 6400;         // 6400
    float* w0a   = h_s + 6400;           // 9216 (r: ih)
    float* w0b   = w0a + 9216;           // 9216 (r: hh)
    float* w1a   = w0b + 9216;           // 9216 (z: ih)
    float* w1b   = w1a + 9216;           // 9216 (z: hh)
    int* nodes_s = (int*)(w1b + 9216);

    int t = threadIdx.x;
    int cnt = g_cnt[it];
    int tile0 = blockIdx.x * 64;
    if (tile0 >= cnt) return;
    int nvalid = min(64, cnt - tile0);

    if (t < 64) nodes_s[t] = g_order[tile0 + min(t, nvalid - 1)];
    __syncthreads();
#pragma unroll
    for (int idx = t; idx < 64 * 24; idx += 256) {
        int n = idx / 24, c4 = idx - n * 24;
        int gn = nodes_s[n];
        ((float4*)(agg_s + n * 100))[c4] = ((const float4*)(g_agg + gn * HID))[c4];
        ((float4*)(h_s + n * 100))[c4]   = ((const float4*)(g_h + gn * HID))[c4];
    }
#pragma unroll
    for (int idx = t; idx < 2304; idx += 256) {
        ((float4*)w0a)[idx] = ((const float4*)g_wt_ih)[idx];
        ((float4*)w0b)[idx] = ((const float4*)g_wt_hh)[idx];
        ((float4*)w1a)[idx] = ((const float4*)(g_wt_ih + 9216))[idx];
        ((float4*)w1b)[idx] = ((const float4*)(g_wt_hh + 9216))[idx];
    }
    __syncthreads();

    int cp = t & 15;     // col-pairs {cp, cp+16, cp+32} (cols 2p, 2p+1)
    int ng = t >> 4;     // nodes 4ng..4ng+3
    int nb = 4 * ng;

    u64 accR[3][4], accZ[3][4];
#pragma unroll
    for (int cc = 0; cc < 3; cc++) {
        int c2 = 2 * (cp + 16 * cc);
        float2 bi0 = *(const float2*)&bih[c2];
        float2 bh0 = *(const float2*)&bhh[c2];
        float2 bi1 = *(const float2*)&bih[96 + c2];
        float2 bh1 = *(const float2*)&bhh[96 + c2];
        u64 bR = pack2(bi0.x + bh0.x, bi0.y + bh0.y);
        u64 bZ = pack2(bi1.x + bh1.x, bi1.y + bh1.y);
#pragma unroll
        for (int q = 0; q < 4; q++) { accR[cc][q] = bR; accZ[cc][q] = bZ; }
    }
#pragma unroll 4
    for (int k = 0; k < 96; k++) {
        u64 wra[3], wrb[3], wza[3], wzb[3];
#pragma unroll
        for (int cc = 0; cc < 3; cc++) {
            int o = k * 96 + 2 * (cp + 16 * cc);
            wra[cc] = *(const u64*)&w0a[o];
            wrb[cc] = *(const u64*)&w0b[o];
            wza[cc] = *(const u64*)&w1a[o];
            wzb[cc] = *(const u64*)&w1b[o];
        }
        u64 a2[4], h2[4];
#pragma unroll
        for (int q = 0; q < 4; q++) {
            float a  = agg_s[(nb + q) * 100 + k];
            float hv = h_s[(nb + q) * 100 + k];
            a2[q] = pack2(a, a);
            h2[q] = pack2(hv, hv);
        }
#pragma unroll
        for (int cc = 0; cc < 3; cc++)
#pragma unroll
            for (int q = 0; q < 4; q++) {
                accR[cc][q] = ffma2(wra[cc], a2[q], accR[cc][q]);
                accR[cc][q] = ffma2(wrb[cc], h2[q], accR[cc][q]);
                accZ[cc][q] = ffma2(wza[cc], a2[q], accZ[cc][q]);
                accZ[cc][q] = ffma2(wzb[cc], h2[q], accZ[cc][q]);
            }
    }
    u64 r_g[3][4], z_g[3][4];
#pragma unroll
    for (int cc = 0; cc < 3; cc++)
#pragma unroll
        for (int q = 0; q < 4; q++) {
            float2 gr = unpack2(accR[cc][q]);
            float2 gz = unpack2(accZ[cc][q]);
            r_g[cc][q] = pack2(fast_sigmoid(gr.x), fast_sigmoid(gr.y));
            z_g[cc][q] = pack2(fast_sigmoid(gz.x), fast_sigmoid(gz.y));
        }

    // chunk 2: candidate gate
    __syncthreads();
#pragma unroll
    for (int idx = t; idx < 2304; idx += 256) {
        ((float4*)w0a)[idx] = ((const float4*)(g_wt_ih + 18432))[idx];
        ((float4*)w0b)[idx] = ((const float4*)(g_wt_hh + 18432))[idx];
    }
    __syncthreads();

    u64 ai[3][4], ah[3][4];
#pragma unroll
    for (int cc = 0; cc < 3; cc++) {
        int c2 = 2 * (cp + 16 * cc);
        float2 b1 = *(const float2*)&bih[192 + c2];
        float2 b2 = *(const float2*)&bhh[192 + c2];
        u64 p1 = pack2(b1.x, b1.y), p2 = pack2(b2.x, b2.y);
#pragma unroll
        for (int q = 0; q < 4; q++) { ai[cc][q] = p1; ah[cc][q] = p2; }
    }
#pragma unroll 4
    for (int k = 0; k < 96; k++) {
        u64 wa[3], wb[3];
#pragma unroll
        for (int cc = 0; cc < 3; cc++) {
            int o = k * 96 + 2 * (cp + 16 * cc);
            wa[cc] = *(const u64*)&w0a[o];
            wb[cc] = *(const u64*)&w0b[o];
        }
        u64 a2[4], h2[4];
#pragma unroll
        for (int q = 0; q < 4; q++) {
            float a  = agg_s[(nb + q) * 100 + k];
            float hv = h_s[(nb + q) * 100 + k];
            a2[q] = pack2(a, a);
            h2[q] = pack2(hv, hv);
        }
#pragma unroll
        for (int cc = 0; cc < 3; cc++)
#pragma unroll
            for (int q = 0; q < 4; q++) {
                ai[cc][q] = ffma2(wa[cc], a2[q], ai[cc][q]);
                ah[cc][q] = ffma2(wb[cc], h2[q], ah[cc][q]);
            }
    }
#pragma unroll
    for (int cc = 0; cc < 3; cc++) {
        int c2 = 2 * (cp + 16 * cc);
#pragma unroll
        for (int q = 0; q < 4; q++) {
            int n = nb + q;
            float2 vi = unpack2(ai[cc][q]);
            float2 vh = unpack2(ah[cc][q]);
            float2 rr = unpack2(r_g[cc][q]);
            float2 zz = unpack2(z_g[cc][q]);
            float hold0 = h_s[n * 100 + c2];
            float hold1 = h_s[n * 100 + c2 + 1];
            float nv0 = fast_tanh(vi.x + rr.x * vh.x);
            float nv1 = fast_tanh(vi.y + rr.y * vh.y);
            float h0 = (1.f - zz.x) * nv0 + zz.x * hold0;
            float h1 = (1.f - zz.y) * nv1 + zz.y * hold1;
            *(float2*)&g_h[nodes_s[n] * HID + c2] = make_float2(h0, h1);
        }
    }
}

// ---------------- output GEMM: k-paired f32x2 ----------------
// ws2 transposed [j][98]; hs [n][98]; per 2k: 1 LDS.64(w) + 8 broadcast LDS.64(h) + 8 FFMA2
__global__ __launch_bounds__(256) void k_out(
    const float* __restrict__ wo, const float* __restrict__ bo,
    float* __restrict__ out)
{
    __shared__ float ws2[64 * 98];
    __shared__ float hs[32 * 98];
    int t = threadIdx.x;
    int node0 = blockIdx.x * 32;
#pragma unroll
    for (int idx = t; idx < 96 * 64; idx += 256) {
        int k = idx >> 6, j = idx & 63;
        ws2[j * 98 + k] = wo[idx];
    }
#pragma unroll
    for (int idx = t; idx < 32 * 96; idx += 256) {
        int n = idx / 96, k = idx - n * 96;
        int gn = node0 + n;
        hs[n * 98 + k] = (gn < N_NODES) ? g_h[gn * HID + k] : 0.f;
    }
    __syncthreads();
    int j = t & 63, nt = t >> 6;
    u64 acc[8];
#pragma unroll
    for (int nn = 0; nn < 8; nn++) acc[nn] = 0;
#pragma unroll 4
    for (int kp = 0; kp < 48; kp++) {
        u64 w2 = *(const u64*)&ws2[j * 98 + 2 * kp];
#pragma unroll
        for (int nn = 0; nn < 8; nn++) {
            u64 h2 = *(const u64*)&hs[(nt + 4 * nn) * 98 + 2 * kp];
            acc[nn] = ffma2(w2, h2, acc[nn]);
        }
    }
    float b = bo[j];
#pragma unroll
    for (int nn = 0; nn < 8; nn++) {
        int gn = node0 + nt + 4 * nn;
        if (gn < N_NODES) {
            float2 s = unpack2(acc[nn]);
            out[gn * OUT_DIM + j] = s.x + s.y + b;
        }
    }
}

// ---------------- launch ----------------
extern "C" void kernel_launch(void* const* d_in, const int* in_sizes, int n_in,
                              void* d_out, int out_size)
{
    const float* x    = (const float*)d_in[0];
    const int*   ei   = (const int*)d_in[1];
    const float* w_in = (const float*)d_in[2];
    const float* b_in = (const float*)d_in[3];
    const float* tw1  = (const float*)d_in[4];
    const float* tb1  = (const float*)d_in[5];
    const float* tw2  = (const float*)d_in[6];
    const float* tb2  = (const float*)d_in[7];
    const float* wih  = (const float*)d_in[8];
    const float* whh  = (const float*)d_in[9];
    const float* bih  = (const float*)d_in[10];
    const float* bhh  = (const float*)d_in[11];
    const float* wo   = (const float*)d_in[12];
    const float* bo   = (const float*)d_in[13];
    float* out = (float*)d_out;

    const int smem_in  = (128 * 66 + 128 * 16) * 4;                     // 41984 B
    const int smem_gru = (6400 * 2 + 9216 * 4) * 4 + 64 * 4;            // 198912 B
    cudaFuncSetAttribute(k_input, cudaFuncAttributeMaxDynamicSharedMemorySize, smem_in);
    cudaFuncSetAttribute(k_gru,   cudaFuncAttributeMaxDynamicSharedMemorySize, smem_gru);

    k_initwt<<<(N_NODES + 255) / 256, 256>>>(wih, whh);               // 1
    k_deg<<<(N_EDGES + 255) / 256, 256>>>(ei);                        // 2
    k_scan1<<<SCAN_NB, 1024>>>();                                     // 3
    k_input<<<(N_NODES + 63) / 64, 256, smem_in>>>(x, w_in, b_in,     // 4 (profiled)
                                                   tw1, tb1, tw2, tb2);
    k_scan2<<<1, 64>>>();                                             // 5
    k_scan3<<<SCAN_NB, 1024>>>();                                     // 6 (+order)
    k_csr<<<(N_EDGES + 255) / 256, 256>>>(ei);                        // 7

    for (int it = 0; it < MAX_REC; it++) {
        k_agg<<<(N_NODES + 7) / 8, 256>>>(it);
        k_gru<<<(N_NODES + 63) / 64, 256, smem_gru>>>(bih, bhh, it);
    }
    k_out<<<(N_NODES + 31) / 32, 256>>>(wo, bo, out);
}

// round 14
// speedup vs baseline: 1.2434x; 1.0312x over previous
#include <cuda_runtime.h>
#include <math.h>

#define N_NODES 50000
#define N_EDGES 800000
#define IN_DIM  128
#define HID     96
#define OUT_DIM 64
#define MAX_REC 5
#define SCAN_NB ((N_NODES + 1023) / 1024)   // 49

typedef unsigned long long u64;

// ---------------- scratch (no allocations allowed) ----------------
__device__ float g_h[N_NODES * HID];
__device__ float g_agg[N_NODES * HID];
__device__ int   g_steps[N_NODES];
__device__ int   g_deg[N_NODES];
__device__ int   g_rowoff[N_NODES + 1];
__device__ int   g_cursor[N_NODES];
__device__ int   g_col[N_EDGES];
__device__ int   g_hist[8];
__device__ int   g_bcur[8];
__device__ int   g_order[N_NODES];
__device__ int   g_cnt[8];
__device__ int   g_bsum[64];
__device__ int   g_boff[64];
__device__ float g_wt_ih[3 * HID * HID];   // [chunk][k][j]
__device__ float g_wt_hh[3 * HID * HID];

// ---------------- f32x2 helpers ----------------
__device__ __forceinline__ u64 ffma2(u64 a, u64 b, u64 c) {
    u64 d;
    asm("fma.rn.f32x2 %0, %1, %2, %3;" : "=l"(d) : "l"(a), "l"(b), "l"(c));
    return d;
}
__device__ __forceinline__ u64 pack2(float x, float y) {
    u64 r;
    asm("mov.b64 %0, {%1, %2};" : "=l"(r) : "f"(x), "f"(y));
    return r;
}
__device__ __forceinline__ float2 unpack2(u64 v) {
    float2 r;
    asm("mov.b64 {%0, %1}, %2;" : "=f"(r.x), "=f"(r.y) : "l"(v));
    return r;
}
__device__ __forceinline__ float fast_sigmoid(float x) {
    return __fdividef(1.f, 1.f + __expf(-x));
}
__device__ __forceinline__ float fast_tanh(float x) {
    return 1.f - __fdividef(2.f, __expf(2.f * x) + 1.f);
}

// ---------------- fused init + weight transpose ----------------
__global__ void k_initwt(const float* __restrict__ wih, const float* __restrict__ whh) {
    int i = blockIdx.x * 256 + threadIdx.x;
    if (i < N_NODES) g_deg[i] = 0;
    if (i < 8) g_hist[i] = 0;
    if (i < 3 * HID * HID) {
        int chunk = i / (HID * HID);
        int r = i - chunk * HID * HID;
        int k = r / HID, j = r - k * HID;
        g_wt_ih[i] = wih[(chunk * HID + j) * HID + k];
        g_wt_hh[i] = whh[(chunk * HID + j) * HID + k];
    }
}

// ---------------- degree histogram ----------------
__global__ void k_deg(const int* __restrict__ ei) {
    int e = blockIdx.x * blockDim.x + threadIdx.x;
    if (e < N_EDGES) atomicAdd(&g_deg[ei[e]], 1);
}

// ---------------- multi-block scan ----------------
__global__ __launch_bounds__(1024) void k_scan1() {
    __shared__ int wsum[32];
    __shared__ int woff[32];
    int t = threadIdx.x, lane = t & 31, wid = t >> 5;
    int i = blockIdx.x * 1024 + t;
    int v = (i < N_NODES) ? g_deg[i] : 0;
    int s = v;
#pragma unroll
    for (int o = 1; o < 32; o <<= 1) {
        int u = __shfl_up_sync(0xffffffffu, s, o);
        if (lane >= o) s += u;
    }
    if (lane == 31) wsum[wid] = s;
    __syncthreads();
    if (wid == 0) {
        int ws = wsum[lane];
        int ss = ws;
#pragma unroll
        for (int o = 1; o < 32; o <<= 1) {
            int u = __shfl_up_sync(0xffffffffu, ss, o);
            if (lane >= o) ss += u;
        }
        woff[lane] = ss - ws;
        if (lane == 31) g_bsum[blockIdx.x] = ss;
    }
    __syncthreads();
    if (i < N_NODES) g_rowoff[i] = s - v + woff[wid];
}

// ---------------- fused input GEMM + relu + tau/steps (R7 exact) ----------------
__global__ __launch_bounds__(256) void k_input(
    const float* __restrict__ x, const float* __restrict__ w_in,
    const float* __restrict__ b_in, const float* __restrict__ tw1,
    const float* __restrict__ tb1, const float* __restrict__ tw2,
    const float* __restrict__ tb2)
{
    extern __shared__ float sm_in[];
    float* xs_t = sm_in;               // [128][66]
    float* ts   = xs_t + 128 * 66;     // [128][16]
    int t = threadIdx.x;
    int node0 = blockIdx.x * 64;

#pragma unroll
    for (int idx = t; idx < 128 * 16; idx += 256) ts[idx] = tw1[idx];
#pragma unroll
    for (int idx = t; idx < 64 * 128; idx += 256) {
        int n = idx >> 7, k = idx & 127;
        int gn = node0 + n;
        xs_t[k * 66 + n] = (gn < N_NODES) ? x[gn * IN_DIM + k] : 0.f;
    }
    __syncthreads();

    int cj = t & 31;     // cols {cj, cj+32, cj+64}
    int pg = t >> 5;     // node pairs {pg, pg+8, pg+16, pg+24}

    u64 acc[3][4];
#pragma unroll
    for (int cc = 0; cc < 3; cc++) {
        float b = b_in[cj + 32 * cc];
        u64 bp = pack2(b, b);
#pragma unroll
        for (int q = 0; q < 4; q++) acc[cc][q] = bp;
    }
#pragma unroll 8
    for (int k = 0; k < 128; k++) {
        u64 wd[3];
#pragma unroll
        for (int cc = 0; cc < 3; cc++) {
            float w = __ldg(&w_in[k * 96 + cj + 32 * cc]);
            wd[cc] = pack2(w, w);
        }
        u64 ap[4];
#pragma unroll
        for (int q = 0; q < 4; q++)
            ap[q] = *(const u64*)&xs_t[k * 66 + 2 * (pg + 8 * q)];
#pragma unroll
        for (int cc = 0; cc < 3; cc++)
#pragma unroll
            for (int q = 0; q < 4; q++)
                acc[cc][q] = ffma2(wd[cc], ap[q], acc[cc][q]);
    }
#pragma unroll
    for (int cc = 0; cc < 3; cc++) {
        int col = cj + 32 * cc;
#pragma unroll
        for (int q = 0; q < 4; q++) {
            int n0 = node0 + 2 * (pg + 8 * q);
            float2 g = unpack2(acc[cc][q]);
            if (n0 < N_NODES)     g_h[n0 * HID + col]       = fmaxf(g.x, 0.f);
            if (n0 + 1 < N_NODES) g_h[(n0 + 1) * HID + col] = fmaxf(g.y, 0.f);
        }
    }

    // tau: 4 threads per node (R7 exact)
    {
        int tn = t >> 2;
        int tj = t & 3;
        int gn = node0 + tn;
        float hh[4];
#pragma unroll
        for (int u = 0; u < 4; u++) hh[u] = tb1[tj + 4 * u];
#pragma unroll 4
        for (int k = 0; k < 128; k++) {
            float xv = xs_t[k * 66 + tn];
#pragma unroll
            for (int u = 0; u < 4; u++)
                hh[u] += xv * ts[k * 16 + tj + 4 * u];
        }
        float s = 0.f;
#pragma unroll
        for (int u = 0; u < 4; u++)
            s += fmaxf(hh[u], 0.f) * tw2[tj + 4 * u];
        s += __shfl_xor_sync(0xffffffffu, s, 1);
        s += __shfl_xor_sync(0xffffffffu, s, 2);
        if (tj == 0 && gn < N_NODES) {
            s += tb2[0];
            float sp = fmaxf(s, 0.f) + log1pf(expf(-fabsf(s)));
            float inv = 1.0f / sp;
            int st = (inv >= (float)MAX_REC) ? MAX_REC : (int)inv;
            g_steps[gn] = st;
            atomicAdd(&g_hist[st], 1);
        }
    }
}

__global__ void k_scan2() {
    __shared__ int sh[64];
    int t = threadIdx.x;
    sh[t] = (t < SCAN_NB) ? g_bsum[t] : 0;
    __syncthreads();
    if (t == 0) {
        int run = 0;
        for (int b = 0; b < SCAN_NB; b++) { g_boff[b] = run; run += sh[b]; }
        g_rowoff[N_NODES] = run;
        int suffix = 0;
        int start[6];
        for (int s = 5; s >= 0; s--) { start[s] = suffix; suffix += g_hist[s]; }
        for (int s = 0; s < 6; s++) g_bcur[s] = start[s];
        for (int it = 0; it < 5; it++) g_cnt[it] = start[it];
    }
}

// scan3 + order fused
__global__ __launch_bounds__(1024) void k_scan3() {
    int i = blockIdx.x * 1024 + threadIdx.x;
    if (i < N_NODES) {
        int v = g_rowoff[i] + g_boff[blockIdx.x];
        g_rowoff[i] = v;
        g_cursor[i] = v;
        int s = g_steps[i];
        int pos = atomicAdd(&g_bcur[s], 1);
        g_order[pos] = i;
    }
}

// ---------------- CSR fill ----------------
__global__ void k_csr(const int* __restrict__ ei) {
    int e = blockIdx.x * blockDim.x + threadIdx.x;
    if (e < N_EDGES) {
        int r = ei[e];
        int c = ei[N_EDGES + e];
        int pos = atomicAdd(&g_cursor[r], 1);
        g_col[pos] = c;
    }
}

// ---------------- edge aggregation (R7 exact) ----------------
__global__ __launch_bounds__(256) void k_agg(int it) {
    int w = blockIdx.x * 8 + (threadIdx.x >> 5);
    if (w >= g_cnt[it]) return;
    int node = g_order[w];
    int lane = threadIdx.x & 31;
    int grp = lane >> 2;
    int l4  = lane & 3;
    int base = g_rowoff[node], end = g_rowoff[node + 1];

    const float4* hi4 = (const float4*)(g_h + node * HID);
    float4 hi[6], acc[6];
#pragma unroll
    for (int u = 0; u < 6; u++) {
        hi[u] = hi4[l4 + 4 * u];
        acc[u] = make_float4(0.f, 0.f, 0.f, 0.f);
    }

#pragma unroll 2
    for (int e = base + grp; e < end; e += 8) {
        int cc = __ldg(&g_col[e]);
        const float4* hp = (const float4*)(g_h + cc * HID);
#pragma unroll
        for (int u = 0; u < 6; u++) {
            float4 v = hp[l4 + 4 * u];
            acc[u].x += fabsf(v.x - hi[u].x);
            acc[u].y += fabsf(v.y - hi[u].y);
            acc[u].z += fabsf(v.z - hi[u].z);
            acc[u].w += fabsf(v.w - hi[u].w);
        }
    }
#pragma unroll
    for (int off = 4; off < 32; off <<= 1) {
#pragma unroll
        for (int u = 0; u < 6; u++) {
            acc[u].x += __shfl_xor_sync(0xffffffffu, acc[u].x, off);
            acc[u].y += __shfl_xor_sync(0xffffffffu, acc[u].y, off);
            acc[u].z += __shfl_xor_sync(0xffffffffu, acc[u].z, off);
            acc[u].w += __shfl_xor_sync(0xffffffffu, acc[u].w, off);
        }
    }
    if (grp == 0) {
        float4* ar = (float4*)(g_agg + (long long)node * HID);
#pragma unroll
        for (int u = 0; u < 6; u++) ar[l4 + 4 * u] = acc[u];
    }
}

// ---------------- GRU v3 (R7 exact) ----------------
__global__ __launch_bounds__(256, 1) void k_gru(
    const float* __restrict__ bih, const float* __restrict__ bhh, int it)
{
    extern __shared__ float sm_g[];
    float* agg_s = sm_g;                 // 6400
    float* h_s   = agg_s + 6400;         // 6400
    float* w0a   = h_s + 6400;           // 9216 (r: ih)
    float* w0b   = w0a + 9216;           // 9216 (r: hh)
    float* w1a   = w0b + 9216;           // 9216 (z: ih)
    float* w1b   = w1a + 9216;           // 9216 (z: hh)
    int* nodes_s = (int*)(w1b + 9216);

    int t = threadIdx.x;
    int cnt = g_cnt[it];
    int tile0 = blockIdx.x * 64;
    if (tile0 >= cnt) return;
    int nvalid = min(64, cnt - tile0);

    if (t < 64) nodes_s[t] = g_order[tile0 + min(t, nvalid - 1)];
    __syncthreads();
#pragma unroll
    for (int idx = t; idx < 64 * 24; idx += 256) {
        int n = idx / 24, c4 = idx - n * 24;
        int gn = nodes_s[n];
        ((float4*)(agg_s + n * 100))[c4] = ((const float4*)(g_agg + gn * HID))[c4];
        ((float4*)(h_s + n * 100))[c4]   = ((const float4*)(g_h + gn * HID))[c4];
    }
#pragma unroll
    for (int idx = t; idx < 2304; idx += 256) {
        ((float4*)w0a)[idx] = ((const float4*)g_wt_ih)[idx];
        ((float4*)w0b)[idx] = ((const float4*)g_wt_hh)[idx];
        ((float4*)w1a)[idx] = ((const float4*)(g_wt_ih + 9216))[idx];
        ((float4*)w1b)[idx] = ((const float4*)(g_wt_hh + 9216))[idx];
    }
    __syncthreads();

    int cp = t & 15;     // col-pairs {cp, cp+16, cp+32} (cols 2p, 2p+1)
    int ng = t >> 4;     // nodes 4ng..4ng+3
    int nb = 4 * ng;

    u64 accR[3][4], accZ[3][4];
#pragma unroll
    for (int cc = 0; cc < 3; cc++) {
        int c2 = 2 * (cp + 16 * cc);
        float2 bi0 = *(const float2*)&bih[c2];
        float2 bh0 = *(const float2*)&bhh[c2];
        float2 bi1 = *(const float2*)&bih[96 + c2];
        float2 bh1 = *(const float2*)&bhh[96 + c2];
        u64 bR = pack2(bi0.x + bh0.x, bi0.y + bh0.y);
        u64 bZ = pack2(bi1.x + bh1.x, bi1.y + bh1.y);
#pragma unroll
        for (int q = 0; q < 4; q++) { accR[cc][q] = bR; accZ[cc][q] = bZ; }
    }
#pragma unroll 4
    for (int k = 0; k < 96; k++) {
        u64 wra[3], wrb[3], wza[3], wzb[3];
#pragma unroll
        for (int cc = 0; cc < 3; cc++) {
            int o = k * 96 + 2 * (cp + 16 * cc);
            wra[cc] = *(const u64*)&w0a[o];
            wrb[cc] = *(const u64*)&w0b[o];
            wza[cc] = *(const u64*)&w1a[o];
            wzb[cc] = *(const u64*)&w1b[o];
        }
        u64 a2[4], h2[4];
#pragma unroll
        for (int q = 0; q < 4; q++) {
            float a  = agg_s[(nb + q) * 100 + k];
            float hv = h_s[(nb + q) * 100 + k];
            a2[q] = pack2(a, a);
            h2[q] = pack2(hv, hv);
        }
#pragma unroll
        for (int cc = 0; cc < 3; cc++)
#pragma unroll
            for (int q = 0; q < 4; q++) {
                accR[cc][q] = ffma2(wra[cc], a2[q], accR[cc][q]);
                accR[cc][q] = ffma2(wrb[cc], h2[q], accR[cc][q]);
                accZ[cc][q] = ffma2(wza[cc], a2[q], accZ[cc][q]);
                accZ[cc][q] = ffma2(wzb[cc], h2[q], accZ[cc][q]);
            }
    }
    u64 r_g[3][4], z_g[3][4];
#pragma unroll
    for (int cc = 0; cc < 3; cc++)
#pragma unroll
        for (int q = 0; q < 4; q++) {
            float2 gr = unpack2(accR[cc][q]);
            float2 gz = unpack2(accZ[cc][q]);
            r_g[cc][q] = pack2(fast_sigmoid(gr.x), fast_sigmoid(gr.y));
            z_g[cc][q] = pack2(fast_sigmoid(gz.x), fast_sigmoid(gz.y));
        }

    // chunk 2: candidate gate
    __syncthreads();
#pragma unroll
    for (int idx = t; idx < 2304; idx += 256) {
        ((float4*)w0a)[idx] = ((const float4*)(g_wt_ih + 18432))[idx];
        ((float4*)w0b)[idx] = ((const float4*)(g_wt_hh + 18432))[idx];
    }
    __syncthreads();

    u64 ai[3][4], ah[3][4];
#pragma unroll
    for (int cc = 0; cc < 3; cc++) {
        int c2 = 2 * (cp + 16 * cc);
        float2 b1 = *(const float2*)&bih[192 + c2];
        float2 b2 = *(const float2*)&bhh[192 + c2];
        u64 p1 = pack2(b1.x, b1.y), p2 = pack2(b2.x, b2.y);
#pragma unroll
        for (int q = 0; q < 4; q++) { ai[cc][q] = p1; ah[cc][q] = p2; }
    }
#pragma unroll 4
    for (int k = 0; k < 96; k++) {
        u64 wa[3], wb[3];
#pragma unroll
        for (int cc = 0; cc < 3; cc++) {
            int o = k * 96 + 2 * (cp + 16 * cc);
            wa[cc] = *(const u64*)&w0a[o];
            wb[cc] = *(const u64*)&w0b[o];
        }
        u64 a2[4], h2[4];
#pragma unroll
        for (int q = 0; q < 4; q++) {
            float a  = agg_s[(nb + q) * 100 + k];
            float hv = h_s[(nb + q) * 100 + k];
            a2[q] = pack2(a, a);
            h2[q] = pack2(hv, hv);
        }
#pragma unroll
        for (int cc = 0; cc < 3; cc++)
#pragma unroll
            for (int q = 0; q < 4; q++) {
                ai[cc][q] = ffma2(wa[cc], a2[q], ai[cc][q]);
                ah[cc][q] = ffma2(wb[cc], h2[q], ah[cc][q]);
            }
    }
#pragma unroll
    for (int cc = 0; cc < 3; cc++) {
        int c2 = 2 * (cp + 16 * cc);
#pragma unroll
        for (int q = 0; q < 4; q++) {
            int n = nb + q;
            float2 vi = unpack2(ai[cc][q]);
            float2 vh = unpack2(ah[cc][q]);
            float2 rr = unpack2(r_g[cc][q]);
            float2 zz = unpack2(z_g[cc][q]);
            float hold0 = h_s[n * 100 + c2];
            float hold1 = h_s[n * 100 + c2 + 1];
            float nv0 = fast_tanh(vi.x + rr.x * vh.x);
            float nv1 = fast_tanh(vi.y + rr.y * vh.y);
            float h0 = (1.f - zz.x) * nv0 + zz.x * hold0;
            float h1 = (1.f - zz.y) * nv1 + zz.y * hold1;
            *(float2*)&g_h[nodes_s[n] * HID + c2] = make_float2(h0, h1);
        }
    }
}

// ---------------- output GEMM: k-paired f32x2 (R13, kept) ----------------
__global__ __launch_bounds__(256) void k_out(
    const float* __restrict__ wo, const float* __restrict__ bo,
    float* __restrict__ out)
{
    __shared__ float ws2[64 * 98];
    __shared__ float hs[32 * 98];
    int t = threadIdx.x;
    int node0 = blockIdx.x * 32;
#pragma unroll
    for (int idx = t; idx < 96 * 64; idx += 256) {
        int k = idx >> 6, j = idx & 63;
        ws2[j * 98 + k] = wo[idx];
    }
#pragma unroll
    for (int idx = t; idx < 32 * 96; idx += 256) {
        int n = idx / 96, k = idx - n * 96;
        int gn = node0 + n;
        hs[n * 98 + k] = (gn < N_NODES) ? g_h[gn * HID + k] : 0.f;
    }
    __syncthreads();
    int j = t & 63, nt = t >> 6;
    u64 acc[8];
#pragma unroll
    for (int nn = 0; nn < 8; nn++) acc[nn] = 0;
#pragma unroll 4
    for (int kp = 0; kp < 48; kp++) {
        u64 w2 = *(const u64*)&ws2[j * 98 + 2 * kp];
#pragma unroll
        for (int nn = 0; nn < 8; nn++) {
            u64 h2 = *(const u64*)&hs[(nt + 4 * nn) * 98 + 2 * kp];
            acc[nn] = ffma2(w2, h2, acc[nn]);
        }
    }
    float b = bo[j];
#pragma unroll
    for (int nn = 0; nn < 8; nn++) {
        int gn = node0 + nt + 4 * nn;
        if (gn < N_NODES) {
            float2 s = unpack2(acc[nn]);
            out[gn * OUT_DIM + j] = s.x + s.y + b;
        }
    }
}

// ---------------- launch ----------------
extern "C" void kernel_launch(void* const* d_in, const int* in_sizes, int n_in,
                              void* d_out, int out_size)
{
    const float* x    = (const float*)d_in[0];
    const int*   ei   = (const int*)d_in[1];
    const float* w_in = (const float*)d_in[2];
    const float* b_in = (const float*)d_in[3];
    const float* tw1  = (const float*)d_in[4];
    const float* tb1  = (const float*)d_in[5];
    const float* tw2  = (const float*)d_in[6];
    const float* tb2  = (const float*)d_in[7];
    const float* wih  = (const float*)d_in[8];
    const float* whh  = (const float*)d_in[9];
    const float* bih  = (const float*)d_in[10];
    const float* bhh  = (const float*)d_in[11];
    const float* wo   = (const float*)d_in[12];
    const float* bo   = (const float*)d_in[13];
    float* out = (float*)d_out;

    const int smem_in  = (128 * 66 + 128 * 16) * 4;                     // 41984 B
    const int smem_gru = (6400 * 2 + 9216 * 4) * 4 + 64 * 4;            // 198912 B
    cudaFuncSetAttribute(k_input, cudaFuncAttributeMaxDynamicSharedMemorySize, smem_in);
    cudaFuncSetAttribute(k_gru,   cudaFuncAttributeMaxDynamicSharedMemorySize, smem_gru);

    k_initwt<<<(N_NODES + 255) / 256, 256>>>(wih, whh);               // 1
    k_deg<<<(N_EDGES + 255) / 256, 256>>>(ei);                        // 2
    k_scan1<<<SCAN_NB, 1024>>>();                                     // 3
    k_input<<<(N_NODES + 63) / 64, 256, smem_in>>>(x, w_in, b_in,     // 4 (profiled)
                                                   tw1, tb1, tw2, tb2);
    k_scan2<<<1, 64>>>();                                             // 5
    k_scan3<<<SCAN_NB, 1024>>>();                                     // 6 (+order)
    k_csr<<<(N_EDGES + 255) / 256, 256>>>(ei);                        // 7

    for (int it = 0; it < MAX_REC; it++) {
        k_agg<<<(N_NODES + 7) / 8, 256>>>(it);
        k_gru<<<(N_NODES + 63) / 64, 256, smem_gru>>>(bih, bhh, it);
    }
    k_out<<<(N_NODES + 31) / 32, 256>>>(wo, bo, out);
}